// round 11
// baseline (speedup 1.0000x reference)
#include <cuda_runtime.h>
#include <math.h>
#define LL 4096

__device__ __align__(16) float g_xilc[16384*192];
__device__ __align__(16) float g_z   [16384*192];
__device__ __align__(16) float g_xi  [768*LL];
__device__ __align__(16) float g_xc  [768*LL];
__device__ __align__(16) float g_xcT [768*LL];
__device__ __align__(16) float g_xdbl[16*LL*40];
__device__ __align__(16) float g_ys  [16*192*LL];
__device__ __align__(16) float g_ysum[768*LL];
__device__ __align__(16) float g_ygt [16384*192];
__device__ __align__(16) float g_hcl [16384*768];
__device__ __align__(16) float g_hc2 [16384*768];
__device__ __align__(16) float g_weff[25*768];
__device__ __align__(16) float g_wg  [96*768];
__device__ __align__(16) float g_ps  [16384*12];
__device__ __align__(16) float g_ps2 [16384*12];
__device__ float g_rowm[16384];
__device__ float g_rowr[16384];
__device__ float g_csum[96];
__device__ float g_cb2 [96];

__device__ __forceinline__ float siluf(float v){ return v/(1.f+__expf(-v)); }
__device__ __forceinline__ unsigned f2tf(float f){ unsigned u; asm("cvt.rna.tf32.f32 %0, %1;":"=r"(u):"f"(f)); return u; }
__device__ __forceinline__ void mma8(float* c, unsigned a0,unsigned a1,unsigned a2,unsigned a3,
                                     unsigned b0,unsigned b1){
  asm("mma.sync.aligned.m16n8k8.row.col.f32.tf32.tf32.f32 "
      "{%0,%1,%2,%3},{%4,%5,%6,%7},{%8,%9},{%0,%1,%2,%3};"
      : "+f"(c[0]),"+f"(c[1]),"+f"(c[2]),"+f"(c[3])
      : "r"(a0),"r"(a1),"r"(a2),"r"(a3),"r"(b0),"r"(b1));
}

// C[M,N] = A[M,K]@W[N,K]^T, tf32 tensor cores. 128x128 tile, BK=32, 8 warps (2m x 4n).
// Row stride 48 words; k-chunk j (16 k's) at word offset j*24, k-permuted within chunk.
// MODE 0: plain  1: bias+silu  3: C += skip[0]*((v-rowm[m]*csum[n])*rowr[m]+cb2[n])
// MODE 4: split write: col<192 -> C[m*192+col], col>=192 -> C2[m*192+col-192]
template<int MODE>
__global__ __launch_bounds__(256,2) void gemm_tc(
  const float* __restrict__ A, const float* __restrict__ W, float* __restrict__ C,
  float* __restrict__ C2,
  int M, int N, int K, const float* __restrict__ bias, const float* __restrict__ skip,
  const float* __restrict__ rowm, const float* __restrict__ rowr,
  const float* __restrict__ csum, const float* __restrict__ cb2)
{
  __shared__ unsigned As[128*48];
  __shared__ unsigned Bs[128*48];
  int tid=threadIdx.x, lane=tid&31, warp=tid>>5;
  int wm=warp>>2, wn=warp&3;
  int m0=blockIdx.y*128, n0=blockIdx.x*128;
  int lr=lane>>2, lc=lane&3;
  float acc[4][4][4];
  #pragma unroll
  for(int a=0;a<4;a++)
    #pragma unroll
    for(int b=0;b<4;b++)
      #pragma unroll
      for(int q=0;q<4;q++) acc[a][b][q]=0.f;

  int row0=tid>>1, sg=tid&1;
  float4 ra[4], rb[4];
  {
    int br=n0+row0;
    #pragma unroll
    for(int q=0;q<4;q++){
      int kk=sg*16+q*4;
      ra[q]=*(const float4*)(A+(size_t)(m0+row0)*K+kk);
      rb[q]=(br<N)? *(const float4*)(W+(size_t)br*K+kk) : make_float4(0,0,0,0);
    }
  }
  for(int k0=0;k0<K;k0+=32){
    unsigned* p=&As[row0*48+sg*24];
    unsigned* q2=&Bs[row0*48+sg*24];
    #pragma unroll
    for(int q=0;q<4;q++){
      p[q]=f2tf(ra[q].x); p[4+q]=f2tf(ra[q].y); p[8+q]=f2tf(ra[q].z); p[12+q]=f2tf(ra[q].w);
      q2[q]=f2tf(rb[q].x); q2[4+q]=f2tf(rb[q].y); q2[8+q]=f2tf(rb[q].z); q2[12+q]=f2tf(rb[q].w);
    }
    __syncthreads();
    if(k0+32<K){
      int br=n0+row0;
      #pragma unroll
      for(int q=0;q<4;q++){
        int kk=k0+32+sg*16+q*4;
        ra[q]=*(const float4*)(A+(size_t)(m0+row0)*K+kk);
        rb[q]=(br<N)? *(const float4*)(W+(size_t)br*K+kk) : make_float4(0,0,0,0);
      }
    }
    #pragma unroll
    for(int j=0;j<2;j++){
      uint4 bg[4];
      #pragma unroll
      for(int nt=0;nt<4;nt++) bg[nt]=*(const uint4*)&Bs[(wn*32+nt*8+lr)*48+j*24+lc*4];
      #pragma unroll
      for(int mt=0;mt<4;mt++){
        int r0=wm*64+mt*16+lr;
        uint4 f0=*(const uint4*)&As[r0*48+j*24+lc*4];
        uint4 f1=*(const uint4*)&As[(r0+8)*48+j*24+lc*4];
        #pragma unroll
        for(int nt=0;nt<4;nt++){
          mma8(acc[mt][nt], f0.x,f1.x,f0.y,f1.y, bg[nt].x,bg[nt].y);
          mma8(acc[mt][nt], f0.z,f1.z,f0.w,f1.w, bg[nt].z,bg[nt].w);
        }
      }
    }
    __syncthreads();
  }
  #pragma unroll
  for(int mt=0;mt<4;mt++){
    #pragma unroll
    for(int nt=0;nt<4;nt++){
      int col=n0+wn*32+nt*8+lc*2;
      if(col>=N) continue;
      #pragma unroll
      for(int hh=0;hh<2;hh++){
        int row=m0+wm*64+mt*16+lr+hh*8;
        float v0=acc[mt][nt][hh*2], v1=acc[mt][nt][hh*2+1];
        size_t idx=(size_t)row*N+col;
        if(MODE==0){ C[idx]=v0; C[idx+1]=v1; }
        else if(MODE==1){
          v0+=bias[col]; v1+=bias[col+1];
          C[idx]=siluf(v0); C[idx+1]=siluf(v1);
        } else if(MODE==4){
          if(col<192){ C[(size_t)row*192+col]=v0; C[(size_t)row*192+col+1]=v1; }
          else { C2[(size_t)row*192+col-192]=v0; C2[(size_t)row*192+col-191]=v1; }
        } else {
          float sk=skip[0], mn=rowm[row], rs=rowr[row];
          C[idx]  += sk*((v0-mn*csum[col  ])*rs + cb2[col  ]);
          C[idx+1]+= sk*((v1-mn*csum[col+1])*rs + cb2[col+1]);
        }
      }
    }
  }
}

// xilc[m,c] -> xi [b][c][l]
__global__ void t_xi(){
  __shared__ float t[32][33];
  int b=blockIdx.z, c0=blockIdx.x*32, l0=blockIdx.y*32, tx=threadIdx.x, ty=threadIdx.y;
  for(int i=0;i<4;i++) t[ty+i*8][tx]=g_xilc[((size_t)b*LL+l0+ty+i*8)*192+c0+tx];
  __syncthreads();
  for(int i=0;i<4;i++) g_xi[((size_t)b*192+c0+ty+i*8)*LL+l0+tx]=t[tx][ty+i*8];
}

// depthwise 3x3 + bias + silu, writes both xc (hw) and xcT (wh) coalesced
__global__ __launch_bounds__(256) void conv3t(const float* __restrict__ cw, const float* __restrict__ cb){
  __shared__ float pl[66*66];
  __shared__ float ot[64*65];
  int bc=blockIdx.x, c=bc%192;
  const float* src=g_xi+(size_t)bc*4096;
  float wr[9];
  #pragma unroll
  for(int i=0;i<9;i++) wr[i]=cw[c*9+i];
  float bv=cb[c];
  for(int i=threadIdx.x;i<4356;i+=256){
    int r=i/66, q=i-r*66, h=r-1, w=q-1;
    pl[i]=(h>=0&&h<64&&w>=0&&w<64)? src[h*64+w] : 0.f;
  }
  __syncthreads();
  float* dst=g_xc+(size_t)bc*4096;
  for(int p=threadIdx.x;p<4096;p+=256){
    int h=p>>6, w=p&63;
    float s=bv;
    #pragma unroll
    for(int dy=0;dy<3;dy++)
      #pragma unroll
      for(int dx=0;dx<3;dx++) s+=pl[(h+dy)*66+w+dx]*wr[dy*3+dx];
    s=siluf(s);
    dst[p]=s; ot[h*65+w]=s;
  }
  __syncthreads();
  float* dT=g_xcT+(size_t)bc*4096;
  for(int p=threadIdx.x;p<4096;p+=256){
    int wq=p>>6, hq=p&63;
    dT[p]=ot[hq*65+wq];
  }
}

// x_dbl[bk][l][40]: cols 0..5 dts, 8..39 B/C interleaved (Bn at 8+2n, Cn at 9+2n)
// Register-blocked: 5c x 4l per thread, L-tile 128, K-chunk 32.
__global__ __launch_bounds__(256) void xproj2(const float* __restrict__ xpw){
  __shared__ float Wsm[40*196];
  __shared__ float Xs[32*128];
  int bk=blockIdx.y, b=bk>>2, k=bk&3, l0=blockIdx.x*128, tid=threadIdx.x;
  const float* src=((k&1)?g_xcT:g_xc)+(size_t)b*192*LL;
  bool flip=(k>=2);
  for(int i=tid;i<40*192;i+=256){
    int c=i/192, d=i-c*192;
    Wsm[c*196+d]=(c<38)? xpw[k*38*192+i] : 0.f;
  }
  int tc=tid&7, tl=tid>>3;
  float acc[5][4];
  #pragma unroll
  for(int ci=0;ci<5;ci++)
    #pragma unroll
    for(int j=0;j<4;j++) acc[ci][j]=0.f;
  for(int ch=0;ch<6;ch++){
    __syncthreads();
    for(int i=tid;i<1024;i+=256){
      int d=i>>5, lq=i&31;
      int dg=ch*32+d;
      if(!flip){
        float4 v=*(const float4*)(src+(size_t)dg*LL+l0+lq*4);
        *(float4*)&Xs[d*128+lq*4]=v;
      } else {
        float4 v=*(const float4*)(src+(size_t)dg*LL+4092-l0-lq*4);
        Xs[d*128+lq*4+0]=v.w; Xs[d*128+lq*4+1]=v.z;
        Xs[d*128+lq*4+2]=v.y; Xs[d*128+lq*4+3]=v.x;
      }
    }
    __syncthreads();
    #pragma unroll
    for(int d4=0;d4<8;d4++){
      float4 x0=*(const float4*)&Xs[(d4*4+0)*128+tl*4];
      float4 x1=*(const float4*)&Xs[(d4*4+1)*128+tl*4];
      float4 x2=*(const float4*)&Xs[(d4*4+2)*128+tl*4];
      float4 x3=*(const float4*)&Xs[(d4*4+3)*128+tl*4];
      #pragma unroll
      for(int ci=0;ci<5;ci++){
        float4 wv=*(const float4*)&Wsm[(tc*5+ci)*196+ch*32+d4*4];
        acc[ci][0]+=wv.x*x0.x+wv.y*x1.x+wv.z*x2.x+wv.w*x3.x;
        acc[ci][1]+=wv.x*x0.y+wv.y*x1.y+wv.z*x2.y+wv.w*x3.y;
        acc[ci][2]+=wv.x*x0.z+wv.y*x1.z+wv.z*x2.z+wv.w*x3.z;
        acc[ci][3]+=wv.x*x0.w+wv.y*x1.w+wv.z*x2.w+wv.w*x3.w;
      }
    }
  }
  #pragma unroll
  for(int ci=0;ci<5;ci++){
    int c=tc*5+ci; if(c>=38) continue;
    int col=(c<6)?c:(c<22?(8+2*(c-6)):(9+2*(c-22)));
    #pragma unroll
    for(int j=0;j<4;j++){
      int l=l0+tl*4+j;
      g_xdbl[((size_t)bk*LL+l)*40+col]=acc[ci][j];
    }
  }
}

// scan with fused delta: block = 8 warps = 16 channels of one bk.
// Stages full 40-col x_dbl rows via cp.async double buffer; computes
// delta = softplus(dts@dtw+dtb) cooperatively into smem per 32-step chunk.
__global__ __launch_bounds__(256) void scan3(const float* __restrict__ A_logs, const float* __restrict__ Ds,
                                             const float* __restrict__ dtw, const float* __restrict__ dtb){
  __shared__ float sbc[2][32][40];
  __shared__ float dsm[32][16];
  __shared__ float ybuf[8][2][32];
  int tid=threadIdx.x, wIB=tid>>5, lane=tid&31;
  int bx=blockIdx.x, bk=bx/12, dgrp=bx%12;
  int b=bk>>2, k=bk&3;
  int half=lane>>4, n=lane&15;
  int d=dgrp*16+wIB*2+half, kd=k*192+d;
  float Av=-__expf(A_logs[kd*16+n]), Dv=Ds[kd];
  const float* xsrc=((k&1)?g_xcT:g_xc)+((size_t)b*192+d)*LL;
  const float* xdb=g_xdbl+(size_t)bk*LL*40;
  bool flip=(k>=2);
  // delta-compute assignment: thread handles v0=2*tid, v1=2*tid+1
  int ch0=(2*tid)&15, ch1=(2*tid+1)&15;
  int dd0=dgrp*16+ch0, dd1=dgrp*16+ch1;
  float w0r[6], w1r[6];
  #pragma unroll
  for(int r=0;r<6;r++){ w0r[r]=dtw[(k*192+dd0)*6+r]; w1r[r]=dtw[(k*192+dd1)*6+r]; }
  float b0v=dtb[k*192+dd0], b1v=dtb[k*192+dd1];
  int l_0=(2*tid)>>4, l_1=(2*tid+1)>>4;
  float h=0.f;
  // stage chunk 0: 32 rows x 160B = 320 x 16B
  {
    #pragma unroll
    for(int i=0;i<2;i++){
      int idx=tid+i*256;
      if(idx<320){
        int row=idx/10, seg=idx%10;
        unsigned sa=(unsigned)__cvta_generic_to_shared(&sbc[0][row][seg*4]);
        asm volatile("cp.async.ca.shared.global [%0], [%1], 16;"::"r"(sa),"l"(xdb+row*40+seg*4));
      }
    }
    asm volatile("cp.async.commit_group;");
  }
  for(int ch=0;ch<128;ch++){
    if(ch+1<128){
      const float* s0=xdb+(size_t)(ch+1)*32*40;
      int nb=(ch+1)&1;
      #pragma unroll
      for(int i=0;i<2;i++){
        int idx=tid+i*256;
        if(idx<320){
          int row=idx/10, seg=idx%10;
          unsigned sa=(unsigned)__cvta_generic_to_shared(&sbc[nb][row][seg*4]);
          asm volatile("cp.async.ca.shared.global [%0], [%1], 16;"::"r"(sa),"l"(s0+row*40+seg*4));
        }
      }
      asm volatile("cp.async.commit_group;");
      asm volatile("cp.async.wait_group 1;");
    } else {
      asm volatile("cp.async.wait_group 0;");
    }
    __syncthreads();
    int l0=ch*32, buf=ch&1;
    // cooperative delta: 32 steps x 16 channels
    {
      const float* r0=&sbc[buf][l_0][0];
      float s0=b0v;
      #pragma unroll
      for(int r=0;r<6;r++) s0+=r0[r]*w0r[r];
      dsm[l_0][ch0]=(s0>20.f)?s0:log1pf(__expf(s0));
      const float* r1=&sbc[buf][l_1][0];
      float s1=b1v;
      #pragma unroll
      for(int r=0;r<6;r++) s1+=r1[r]*w1r[r];
      dsm[l_1][ch1]=(s1>20.f)?s1:log1pf(__expf(s1));
    }
    __syncthreads();
    int mych=wIB*2+half;
    #pragma unroll
    for(int s4=0;s4<32;s4+=4){
      int lb=l0+s4;
      float xv[4];
      if(!flip){ float4 x4=*(const float4*)(xsrc+lb); xv[0]=x4.x;xv[1]=x4.y;xv[2]=x4.z;xv[3]=x4.w; }
      else     { float4 x4=*(const float4*)(xsrc+4092-lb); xv[0]=x4.w;xv[1]=x4.z;xv[2]=x4.y;xv[3]=x4.x; }
      #pragma unroll
      for(int i=0;i<4;i++){
        float dl=dsm[s4+i][mych];
        float2 bc=*(const float2*)&sbc[buf][s4+i][8+2*n];
        h=h*__expf(dl*Av)+(dl*xv[i])*bc.x;
        float yp=h*bc.y;
        yp+=__shfl_xor_sync(~0u,yp,1); yp+=__shfl_xor_sync(~0u,yp,2);
        yp+=__shfl_xor_sync(~0u,yp,4); yp+=__shfl_xor_sync(~0u,yp,8);
        if(n==0) ybuf[wIB][half][s4+i]=yp+Dv*xv[i];
      }
    }
    __syncwarp();
    #pragma unroll
    for(int hh=0;hh<2;hh++){
      size_t ob=(((size_t)k*4+b)*192+dgrp*16+wIB*2+hh)*LL;
      int pos=flip?(4095-(l0+lane)):(l0+lane);
      g_ys[ob+pos]=ybuf[wIB][hh][lane];
    }
    __syncthreads();
  }
}

// ysum[b][c][h*64+w] = Y0+Y2 at hw + transpose(Y1+Y3)
__global__ void combine(){
  __shared__ float t[32][33];
  int bc=blockIdx.z, w0=blockIdx.x*32, h0=blockIdx.y*32, tx=threadIdx.x, ty=threadIdx.y;
  const float* Y0=g_ys+(size_t)bc*LL;         const float* Y1=g_ys+(size_t)(768+bc)*LL;
  const float* Y2=g_ys+(size_t)(1536+bc)*LL;  const float* Y3=g_ys+(size_t)(2304+bc)*LL;
  for(int i=0;i<4;i++){ int wl=ty+i*8, j=(w0+wl)*64+h0+tx; t[wl][tx]=Y1[j]+Y3[j]; }
  __syncthreads();
  float* o=g_ysum+(size_t)bc*LL;
  for(int i=0;i<4;i++){ int hl=ty+i*8, l=(h0+hl)*64+w0+tx; o[l]=t[tx][hl]+Y0[l]+Y2[l]; }
}

__global__ __launch_bounds__(256) void ln_gate(const float* __restrict__ g, const float* __restrict__ beta){
  __shared__ float t[192][33];
  int b=blockIdx.y, l0=blockIdx.x*32, tid=threadIdx.x;
  for(int i=tid;i<192*32;i+=256) t[i>>5][i&31]=g_ysum[((size_t)b*192+(i>>5))*LL+l0+(i&31)];
  __syncthreads();
  int warp=tid>>5, lane=tid&31;
  for(int q=0;q<4;q++){
    int li=warp*4+q, l=l0+li;
    float s=0.f,s2=0.f,v[6];
    #pragma unroll
    for(int i=0;i<6;i++){ v[i]=t[lane+32*i][li]; s+=v[i]; s2+=v[i]*v[i]; }
    #pragma unroll
    for(int o=16;o;o>>=1){ s+=__shfl_xor_sync(~0u,s,o); s2+=__shfl_xor_sync(~0u,s2,o); }
    float mean=s/192.f, var=s2/192.f-mean*mean, rstd=rsqrtf(var+1e-5f);
    #pragma unroll
    for(int i=0;i<6;i++){ int c=lane+32*i;
      float zz=g_z[((size_t)b*LL+l)*192+c];
      g_ygt[((size_t)b*LL+l)*192+c]=((v[i]-mean)*rstd*g[c]+beta[c])*siluf(zz); }
  }
}

// merged: blocks 0..2 -> weff; blocks 3..98 -> wg/csum/cb2
__global__ __launch_bounds__(256) void prep_all(const float* __restrict__ d1,const float* __restrict__ d3,
                                                const float* __restrict__ d5,const float* __restrict__ fow,
                                                const float* __restrict__ flg,const float* __restrict__ flb,
                                                const float* __restrict__ fob){
  if(blockIdx.x<3){
    int c=blockIdx.x*256+threadIdx.x; if(c>=768) return;
    for(int t=0;t<25;t++){ int dy=t/5,dx=t%5;
      float w=d5[c*25+t];
      if(dy>=1&&dy<=3&&dx>=1&&dx<=3) w+=d3[c*9+(dy-1)*3+(dx-1)];
      if(t==12) w+=d1[c]+1.0f;
      g_weff[t*768+c]=w; }
    return;
  }
  __shared__ float r1[8], r2[8];
  int n=blockIdx.x-3, tid=threadIdx.x;
  float s1=0.f, s2=0.f;
  for(int c=tid;c<768;c+=256){
    float w=fow[n*768+c], wg=w*flg[c];
    g_wg[n*768+c]=wg; s1+=wg; s2+=w*flb[c];
  }
  #pragma unroll
  for(int o=16;o;o>>=1){ s1+=__shfl_xor_sync(~0u,s1,o); s2+=__shfl_xor_sync(~0u,s2,o); }
  int warp=tid>>5, lane=tid&31;
  if(lane==0){ r1[warp]=s1; r2[warp]=s2; }
  __syncthreads();
  if(tid==0){
    float t1=0.f,t2=0.f;
    #pragma unroll
    for(int i=0;i<8;i++){ t1+=r1[i]; t2+=r2[i]; }
    g_csum[n]=t1; g_cb2[n]=t2+fob[n];
  }
}

// fused effective 5x5 depthwise conv + per-pixel partial sum/sumsq over its 64 channels
__global__ __launch_bounds__(512) void conv5(){
  __shared__ float4 tile[8][12][16];
  int cg=blockIdx.x, w0=blockIdx.y*8, b=blockIdx.z>>4, h0=(blockIdx.z&15)*4;
  int tid=threadIdx.x+threadIdx.y*16+threadIdx.z*128;
  for(int t=tid;t<8*12*16;t+=512){
    int r=t/192, cc=(t%192)/16, c4=t&15;
    int h=h0-2+r, w=w0-2+cc;
    float4 v=make_float4(0,0,0,0);
    if(h>=0&&h<64&&w>=0&&w<64)
      v=*(const float4*)(g_hcl+((size_t)(b*LL+h*64+w))*768+cg*64+c4*4);
    tile[r][cc][c4]=v;
  }
  __syncthreads();
  int c4=threadIdx.x, iw=threadIdx.y, ih=threadIdx.z;
  float4 a=make_float4(0,0,0,0);
  #pragma unroll
  for(int dy=0;dy<5;dy++)
    #pragma unroll
    for(int dx=0;dx<5;dx++){
      float4 xv=tile[ih+dy][iw+dx][c4];
      float4 wv=*(const float4*)(g_weff+(dy*5+dx)*768+cg*64+c4*4);
      a.x=fmaf(xv.x,wv.x,a.x); a.y=fmaf(xv.y,wv.y,a.y);
      a.z=fmaf(xv.z,wv.z,a.z); a.w=fmaf(xv.w,wv.w,a.w);
    }
  int px=b*LL+(h0+ih)*64+w0+iw;
  *(float4*)(g_hc2+(size_t)px*768+cg*64+c4*4)=a;
  float s=a.x+a.y+a.z+a.w;
  float s2=a.x*a.x+a.y*a.y+a.z*a.z+a.w*a.w;
  #pragma unroll
  for(int o=1;o<16;o<<=1){ s+=__shfl_xor_sync(~0u,s,o); s2+=__shfl_xor_sync(~0u,s2,o); }
  int lane=tid&31;
  if((lane&15)==0){ g_ps[px*12+cg]=s; g_ps2[px*12+cg]=s2; }
}

__global__ void stats(){
  int px=blockIdx.x*256+threadIdx.x; if(px>=16384) return;
  float s=0.f, s2=0.f;
  #pragma unroll
  for(int j=0;j<12;j++){ s+=g_ps[px*12+j]; s2+=g_ps2[px*12+j]; }
  float mean=s*(1.f/768.f), var=s2*(1.f/768.f)-mean*mean;
  g_rowm[px]=mean; g_rowr[px]=rsqrtf(var+1e-5f);
}

extern "C" void kernel_launch(void* const* d_in, const int* in_sizes, int n_in,
                              void* d_out, int out_size){
  const float* x    =(const float*)d_in[0];
  const float* ipw  =(const float*)d_in[1];
  const float* cw   =(const float*)d_in[2];
  const float* cb   =(const float*)d_in[3];
  const float* xpw  =(const float*)d_in[4];
  const float* dtw  =(const float*)d_in[5];
  const float* dtb  =(const float*)d_in[6];
  const float* alogs=(const float*)d_in[7];
  const float* dsv  =(const float*)d_in[8];
  const float* ong  =(const float*)d_in[9];
  const float* onb  =(const float*)d_in[10];
  const float* opw  =(const float*)d_in[11];
  const float* fiw  =(const float*)d_in[12];
  const float* fib  =(const float*)d_in[13];
  const float* fd1  =(const float*)d_in[14];
  const float* fd3  =(const float*)d_in[15];
  const float* fd5  =(const float*)d_in[16];
  const float* flg  =(const float*)d_in[17];
  const float* flb  =(const float*)d_in[18];
  const float* fow  =(const float*)d_in[19];
  const float* fob  =(const float*)d_in[20];
  const float* skip =(const float*)d_in[21];
  float* out=(float*)d_out;

  float *pxilc,*pz,*pygt,*phcl,*phc2,*pwg,*prm,*prr,*pcs,*pc2;
  cudaGetSymbolAddress((void**)&pxilc,g_xilc);
  cudaGetSymbolAddress((void**)&pz,   g_z);
  cudaGetSymbolAddress((void**)&pygt, g_ygt);
  cudaGetSymbolAddress((void**)&phcl, g_hcl);
  cudaGetSymbolAddress((void**)&phc2, g_hc2);
  cudaGetSymbolAddress((void**)&pwg,  g_wg);
  cudaGetSymbolAddress((void**)&prm,  g_rowm);
  cudaGetSymbolAddress((void**)&prr,  g_rowr);
  cudaGetSymbolAddress((void**)&pcs,  g_csum);
  cudaGetSymbolAddress((void**)&pc2,  g_cb2);

  prep_all<<<99,256>>>(fd1,fd3,fd5,fow,flg,flb,fob);
  gemm_tc<4><<<dim3(3,128),256>>>(x, ipw, pxilc, pz, 16384,384,96, nullptr,nullptr,nullptr,nullptr,nullptr,nullptr);
  t_xi<<<dim3(6,128,4),dim3(32,8)>>>();
  conv3t<<<768,256>>>(cw,cb);
  xproj2<<<dim3(32,16),256>>>(xpw);
  scan3<<<192,256>>>(alogs,dsv,dtw,dtb);
  combine<<<dim3(2,2,768),dim3(32,8)>>>();
  ln_gate<<<dim3(128,4),256>>>(ong,onb);
  gemm_tc<0><<<dim3(1,128),256>>>(pygt, opw, out, nullptr, 16384,96,192, nullptr,nullptr,nullptr,nullptr,nullptr,nullptr);
  gemm_tc<1><<<dim3(6,128),256>>>(pygt, fiw, phcl, nullptr, 16384,768,192, fib,nullptr,nullptr,nullptr,nullptr,nullptr);
  conv5<<<dim3(12,8,64),dim3(16,8,4)>>>();
  stats<<<64,256>>>();
  gemm_tc<3><<<dim3(1,128),256>>>(phc2, pwg, out, nullptr, 16384,96,768, nullptr,skip,prm,prr,pcs,pc2);
}

// round 12
// speedup vs baseline: 1.1234x; 1.1234x over previous
#include <cuda_runtime.h>
#include <math.h>
#define LL 4096

__device__ __align__(16) float g_xilc[16384*192];
__device__ __align__(16) float g_z   [16384*192];
__device__ __align__(16) float g_xi  [768*LL];
__device__ __align__(16) float g_xc  [768*LL];
__device__ __align__(16) float g_xcT [768*LL];
__device__ __align__(16) float g_xdbl[16*LL*40];
__device__ __align__(16) float g_ys  [16*192*LL];
__device__ __align__(16) float g_ysum[768*LL];
__device__ __align__(16) float g_ygt [16384*192];
__device__ __align__(16) float g_hcl [16384*768];
__device__ __align__(16) float g_hc2 [16384*768];
__device__ __align__(16) float g_weff[25*768];
__device__ __align__(16) float g_wg  [96*768];
__device__ __align__(16) float g_ps  [16384*12];
__device__ __align__(16) float g_ps2 [16384*12];
__device__ float g_csum[96];
__device__ float g_cb2 [96];

__device__ __forceinline__ float siluf(float v){ return v/(1.f+__expf(-v)); }
__device__ __forceinline__ unsigned f2tf(float f){ unsigned u; asm("cvt.rna.tf32.f32 %0, %1;":"=r"(u):"f"(f)); return u; }
__device__ __forceinline__ void mma8(float* c, unsigned a0,unsigned a1,unsigned a2,unsigned a3,
                                     unsigned b0,unsigned b1){
  asm("mma.sync.aligned.m16n8k8.row.col.f32.tf32.tf32.f32 "
      "{%0,%1,%2,%3},{%4,%5,%6,%7},{%8,%9},{%0,%1,%2,%3};"
      : "+f"(c[0]),"+f"(c[1]),"+f"(c[2]),"+f"(c[3])
      : "r"(a0),"r"(a1),"r"(a2),"r"(a3),"r"(b0),"r"(b1));
}

// C[M,N] = A[M,K]@W[N,K]^T, tf32 tensor cores. 128x128x16 tile, 8 warps (2m x 4n).
// MODE 0: plain   1: bias+silu
// MODE 3: C += skip[0]*((v - mean_m*csum[n])*rstd_m + cb2[n]); mean/rstd from ps/ps2 partials
// MODE 4: split write: col<192 -> C[m*192+col], col>=192 -> C2[m*192+col-192]
template<int MODE>
__global__ __launch_bounds__(256,2) void gemm_tc(
  const float* __restrict__ A, const float* __restrict__ W, float* __restrict__ C,
  float* __restrict__ C2,
  int M, int N, int K, const float* __restrict__ bias, const float* __restrict__ skip,
  const float* __restrict__ ps, const float* __restrict__ ps2,
  const float* __restrict__ csum, const float* __restrict__ cb2)
{
  __shared__ unsigned As[128*20];
  __shared__ unsigned Bs[128*20];
  __shared__ float smn[128], srs[128];
  int tid=threadIdx.x, lane=tid&31, warp=tid>>5;
  int wm=warp>>2, wn=warp&3;
  int m0=blockIdx.y*128, n0=blockIdx.x*128;
  int lr=lane>>2, lc=lane&3;
  float acc[4][4][4];
  #pragma unroll
  for(int a=0;a<4;a++)
    #pragma unroll
    for(int b=0;b<4;b++)
      #pragma unroll
      for(int q=0;q<4;q++) acc[a][b][q]=0.f;

  if(MODE==3 && tid<128){
    float s=0.f,s2=0.f;
    #pragma unroll
    for(int j=0;j<12;j++){ s+=ps[(size_t)(m0+tid)*12+j]; s2+=ps2[(size_t)(m0+tid)*12+j]; }
    float mean=s*(1.f/768.f), var=s2*(1.f/768.f)-mean*mean;
    smn[tid]=mean; srs[tid]=rsqrtf(var+1e-5f);
  }

  int row0=tid>>2, t0=tid&3;
  float4 ra[2], rb[2];
  #pragma unroll
  for(int i=0;i<2;i++){
    int row=row0+i*64;
    ra[i]=*(const float4*)(A+(size_t)(m0+row)*K + t0*4);
    int br=n0+row;
    rb[i]= (br<N) ? *(const float4*)(W+(size_t)br*K + t0*4) : make_float4(0,0,0,0);
  }
  for(int k0=0;k0<K;k0+=16){
    #pragma unroll
    for(int i=0;i<2;i++){
      int row=row0+i*64;
      unsigned* p=&As[row*20];
      p[t0]=f2tf(ra[i].x); p[4+t0]=f2tf(ra[i].y); p[8+t0]=f2tf(ra[i].z); p[12+t0]=f2tf(ra[i].w);
      unsigned* q=&Bs[row*20];
      q[t0]=f2tf(rb[i].x); q[4+t0]=f2tf(rb[i].y); q[8+t0]=f2tf(rb[i].z); q[12+t0]=f2tf(rb[i].w);
    }
    __syncthreads();
    if(k0+16<K){
      #pragma unroll
      for(int i=0;i<2;i++){
        int row=row0+i*64;
        ra[i]=*(const float4*)(A+(size_t)(m0+row)*K + k0+16 + t0*4);
        int br=n0+row;
        rb[i]= (br<N) ? *(const float4*)(W+(size_t)br*K + k0+16 + t0*4) : make_float4(0,0,0,0);
      }
    }
    uint4 bg[4];
    #pragma unroll
    for(int nt=0;nt<4;nt++) bg[nt]=*(const uint4*)&Bs[(wn*32+nt*8+lr)*20+lc*4];
    #pragma unroll
    for(int mt=0;mt<4;mt++){
      int r0=wm*64+mt*16+lr;
      uint4 f0=*(const uint4*)&As[r0*20+lc*4];
      uint4 f1=*(const uint4*)&As[(r0+8)*20+lc*4];
      #pragma unroll
      for(int nt=0;nt<4;nt++){
        mma8(acc[mt][nt], f0.x,f1.x,f0.y,f1.y, bg[nt].x,bg[nt].y);
        mma8(acc[mt][nt], f0.z,f1.z,f0.w,f1.w, bg[nt].z,bg[nt].w);
      }
    }
    __syncthreads();
  }
  #pragma unroll
  for(int mt=0;mt<4;mt++){
    #pragma unroll
    for(int nt=0;nt<4;nt++){
      int col=n0+wn*32+nt*8+lc*2;
      if(col>=N) continue;
      #pragma unroll
      for(int hh=0;hh<2;hh++){
        int rloc=wm*64+mt*16+lr+hh*8;
        int row=m0+rloc;
        float v0=acc[mt][nt][hh*2], v1=acc[mt][nt][hh*2+1];
        size_t idx=(size_t)row*N+col;
        if(MODE==0){ C[idx]=v0; C[idx+1]=v1; }
        else if(MODE==1){
          v0+=bias[col]; v1+=bias[col+1];
          C[idx]=siluf(v0); C[idx+1]=siluf(v1);
        } else if(MODE==4){
          if(col<192){ C[(size_t)row*192+col]=v0; C[(size_t)row*192+col+1]=v1; }
          else { C2[(size_t)row*192+col-192]=v0; C2[(size_t)row*192+col-191]=v1; }
        } else {
          float sk=skip[0], mn=smn[rloc], rs=srs[rloc];
          C[idx]  += sk*((v0-mn*csum[col  ])*rs + cb2[col  ]);
          C[idx+1]+= sk*((v1-mn*csum[col+1])*rs + cb2[col+1]);
        }
      }
    }
  }
}

// xilc[m,c] -> xi [b][c][l]
__global__ void t_xi(){
  __shared__ float t[32][33];
  int b=blockIdx.z, c0=blockIdx.x*32, l0=blockIdx.y*32, tx=threadIdx.x, ty=threadIdx.y;
  for(int i=0;i<4;i++) t[ty+i*8][tx]=g_xilc[((size_t)b*LL+l0+ty+i*8)*192+c0+tx];
  __syncthreads();
  for(int i=0;i<4;i++) g_xi[((size_t)b*192+c0+ty+i*8)*LL+l0+tx]=t[tx][ty+i*8];
}

// depthwise 3x3 + bias + silu, writes both xc (hw) and xcT (wh) coalesced
__global__ __launch_bounds__(256) void conv3t(const float* __restrict__ cw, const float* __restrict__ cb){
  __shared__ float pl[66*66];
  __shared__ float ot[64*65];
  int bc=blockIdx.x, c=bc%192;
  const float* src=g_xi+(size_t)bc*4096;
  float wr[9];
  #pragma unroll
  for(int i=0;i<9;i++) wr[i]=cw[c*9+i];
  float bv=cb[c];
  for(int i=threadIdx.x;i<4356;i+=256){
    int r=i/66, q=i-r*66, h=r-1, w=q-1;
    pl[i]=(h>=0&&h<64&&w>=0&&w<64)? src[h*64+w] : 0.f;
  }
  __syncthreads();
  float* dst=g_xc+(size_t)bc*4096;
  for(int p=threadIdx.x;p<4096;p+=256){
    int h=p>>6, w=p&63;
    float s=bv;
    #pragma unroll
    for(int dy=0;dy<3;dy++)
      #pragma unroll
      for(int dx=0;dx<3;dx++) s+=pl[(h+dy)*66+w+dx]*wr[dy*3+dx];
    s=siluf(s);
    dst[p]=s; ot[h*65+w]=s;
  }
  __syncthreads();
  float* dT=g_xcT+(size_t)bc*4096;
  for(int p=threadIdx.x;p<4096;p+=256){
    int wq=p>>6, hq=p&63;
    dT[p]=ot[hq*65+wq];
  }
}

// x_dbl[bk][l][40]: cols 0..5 dts, 8..39 B/C interleaved (Bn at 8+2n, Cn at 9+2n)
// Register-blocked: 5c x 4l per thread, L-tile 128, K-chunk 32.
__global__ __launch_bounds__(256) void xproj2(const float* __restrict__ xpw){
  __shared__ float Wsm[40*196];
  __shared__ float Xs[32*128];
  int bk=blockIdx.y, b=bk>>2, k=bk&3, l0=blockIdx.x*128, tid=threadIdx.x;
  const float* src=((k&1)?g_xcT:g_xc)+(size_t)b*192*LL;
  bool flip=(k>=2);
  for(int i=tid;i<40*192;i+=256){
    int c=i/192, d=i-c*192;
    Wsm[c*196+d]=(c<38)? xpw[k*38*192+i] : 0.f;
  }
  int tc=tid&7, tl=tid>>3;
  float acc[5][4];
  #pragma unroll
  for(int ci=0;ci<5;ci++)
    #pragma unroll
    for(int j=0;j<4;j++) acc[ci][j]=0.f;
  for(int ch=0;ch<6;ch++){
    __syncthreads();
    for(int i=tid;i<1024;i+=256){
      int d=i>>5, lq=i&31;
      int dg=ch*32+d;
      if(!flip){
        float4 v=*(const float4*)(src+(size_t)dg*LL+l0+lq*4);
        *(float4*)&Xs[d*128+lq*4]=v;
      } else {
        float4 v=*(const float4*)(src+(size_t)dg*LL+4092-l0-lq*4);
        Xs[d*128+lq*4+0]=v.w; Xs[d*128+lq*4+1]=v.z;
        Xs[d*128+lq*4+2]=v.y; Xs[d*128+lq*4+3]=v.x;
      }
    }
    __syncthreads();
    #pragma unroll
    for(int d4=0;d4<8;d4++){
      float4 x0=*(const float4*)&Xs[(d4*4+0)*128+tl*4];
      float4 x1=*(const float4*)&Xs[(d4*4+1)*128+tl*4];
      float4 x2=*(const float4*)&Xs[(d4*4+2)*128+tl*4];
      float4 x3=*(const float4*)&Xs[(d4*4+3)*128+tl*4];
      #pragma unroll
      for(int ci=0;ci<5;ci++){
        float4 wv=*(const float4*)&Wsm[(tc*5+ci)*196+ch*32+d4*4];
        acc[ci][0]+=wv.x*x0.x+wv.y*x1.x+wv.z*x2.x+wv.w*x3.x;
        acc[ci][1]+=wv.x*x0.y+wv.y*x1.y+wv.z*x2.y+wv.w*x3.y;
        acc[ci][2]+=wv.x*x0.z+wv.y*x1.z+wv.z*x2.z+wv.w*x3.z;
        acc[ci][3]+=wv.x*x0.w+wv.y*x1.w+wv.z*x2.w+wv.w*x3.w;
      }
    }
  }
  #pragma unroll
  for(int ci=0;ci<5;ci++){
    int c=tc*5+ci; if(c>=38) continue;
    int col=(c<6)?c:(c<22?(8+2*(c-6)):(9+2*(c-22)));
    #pragma unroll
    for(int j=0;j<4;j++){
      int l=l0+tl*4+j;
      g_xdbl[((size_t)bk*LL+l)*40+col]=acc[ci][j];
    }
  }
}

// scan with fused delta: block = 4 warps = 8 channels of one bk.
// Stages full 40-col x_dbl rows via cp.async double buffer; computes
// delta = softplus(dts@dtw+dtb) cooperatively into smem per 32-step chunk.
__global__ __launch_bounds__(128) void scan3(const float* __restrict__ A_logs, const float* __restrict__ Ds,
                                             const float* __restrict__ dtw, const float* __restrict__ dtb){
  __shared__ float sbc[2][32][40];
  __shared__ float dsm[32][8];
  __shared__ float ybuf[4][2][32];
  int tid=threadIdx.x, wIB=tid>>5, lane=tid&31;
  int bx=blockIdx.x, bk=bx/24, dgrp=bx%24;
  int b=bk>>2, k=bk&3;
  int half=lane>>4, n=lane&15;
  int d=dgrp*8+wIB*2+half, kd=k*192+d;
  float Av=-__expf(A_logs[kd*16+n]), Dv=Ds[kd];
  const float* xsrc=((k&1)?g_xcT:g_xc)+((size_t)b*192+d)*LL;
  const float* xdb=g_xdbl+(size_t)bk*LL*40;
  bool flip=(k>=2);
  int ch0=(2*tid)&7, ch1=(2*tid+1)&7;
  int dd0=dgrp*8+ch0, dd1=dgrp*8+ch1;
  float w0r[6], w1r[6];
  #pragma unroll
  for(int r=0;r<6;r++){ w0r[r]=dtw[(k*192+dd0)*6+r]; w1r[r]=dtw[(k*192+dd1)*6+r]; }
  float b0v=dtb[k*192+dd0], b1v=dtb[k*192+dd1];
  int l_0=(2*tid)>>3, l_1=(2*tid+1)>>3;
  float h=0.f;
  {
    #pragma unroll
    for(int i=0;i<3;i++){
      int idx=tid+i*128;
      if(idx<320){
        int row=idx/10, seg=idx%10;
        unsigned sa=(unsigned)__cvta_generic_to_shared(&sbc[0][row][seg*4]);
        asm volatile("cp.async.ca.shared.global [%0], [%1], 16;"::"r"(sa),"l"(xdb+row*40+seg*4));
      }
    }
    asm volatile("cp.async.commit_group;");
  }
  for(int ch=0;ch<128;ch++){
    if(ch+1<128){
      const float* s0=xdb+(size_t)(ch+1)*32*40;
      int nb=(ch+1)&1;
      #pragma unroll
      for(int i=0;i<3;i++){
        int idx=tid+i*128;
        if(idx<320){
          int row=idx/10, seg=idx%10;
          unsigned sa=(unsigned)__cvta_generic_to_shared(&sbc[nb][row][seg*4]);
          asm volatile("cp.async.ca.shared.global [%0], [%1], 16;"::"r"(sa),"l"(s0+row*40+seg*4));
        }
      }
      asm volatile("cp.async.commit_group;");
      asm volatile("cp.async.wait_group 1;");
    } else {
      asm volatile("cp.async.wait_group 0;");
    }
    __syncthreads();
    int l0=ch*32, buf=ch&1;
    {
      const float* r0=&sbc[buf][l_0][0];
      float s0=b0v;
      #pragma unroll
      for(int r=0;r<6;r++) s0+=r0[r]*w0r[r];
      dsm[l_0][ch0]=(s0>20.f)?s0:log1pf(__expf(s0));
      const float* r1=&sbc[buf][l_1][0];
      float s1=b1v;
      #pragma unroll
      for(int r=0;r<6;r++) s1+=r1[r]*w1r[r];
      dsm[l_1][ch1]=(s1>20.f)?s1:log1pf(__expf(s1));
    }
    __syncthreads();
    int mych=wIB*2+half;
    #pragma unroll
    for(int s4=0;s4<32;s4+=4){
      int lb=l0+s4;
      float xv[4];
      if(!flip){ float4 x4=*(const float4*)(xsrc+lb); xv[0]=x4.x;xv[1]=x4.y;xv[2]=x4.z;xv[3]=x4.w; }
      else     { float4 x4=*(const float4*)(xsrc+4092-lb); xv[0]=x4.w;xv[1]=x4.z;xv[2]=x4.y;xv[3]=x4.x; }
      #pragma unroll
      for(int i=0;i<4;i++){
        float dl=dsm[s4+i][mych];
        float2 bc=*(const float2*)&sbc[buf][s4+i][8+2*n];
        h=h*__expf(dl*Av)+(dl*xv[i])*bc.x;
        float yp=h*bc.y;
        yp+=__shfl_xor_sync(~0u,yp,1); yp+=__shfl_xor_sync(~0u,yp,2);
        yp+=__shfl_xor_sync(~0u,yp,4); yp+=__shfl_xor_sync(~0u,yp,8);
        if(n==0) ybuf[wIB][half][s4+i]=yp+Dv*xv[i];
      }
    }
    __syncwarp();
    #pragma unroll
    for(int hh=0;hh<2;hh++){
      size_t ob=(((size_t)k*4+b)*192+dgrp*8+wIB*2+hh)*LL;
      int pos=flip?(4095-(l0+lane)):(l0+lane);
      g_ys[ob+pos]=ybuf[wIB][hh][lane];
    }
    __syncthreads();
  }
}

// ysum[b][c][h*64+w] = Y0+Y2 at hw + transpose(Y1+Y3)
__global__ void combine(){
  __shared__ float t[32][33];
  int bc=blockIdx.z, w0=blockIdx.x*32, h0=blockIdx.y*32, tx=threadIdx.x, ty=threadIdx.y;
  const float* Y0=g_ys+(size_t)bc*LL;         const float* Y1=g_ys+(size_t)(768+bc)*LL;
  const float* Y2=g_ys+(size_t)(1536+bc)*LL;  const float* Y3=g_ys+(size_t)(2304+bc)*LL;
  for(int i=0;i<4;i++){ int wl=ty+i*8, j=(w0+wl)*64+h0+tx; t[wl][tx]=Y1[j]+Y3[j]; }
  __syncthreads();
  float* o=g_ysum+(size_t)bc*LL;
  for(int i=0;i<4;i++){ int hl=ty+i*8, l=(h0+hl)*64+w0+tx; o[l]=t[tx][hl]+Y0[l]+Y2[l]; }
}

__global__ __launch_bounds__(256) void ln_gate(const float* __restrict__ g, const float* __restrict__ beta){
  __shared__ float t[192][33];
  int b=blockIdx.y, l0=blockIdx.x*32, tid=threadIdx.x;
  for(int i=tid;i<192*32;i+=256) t[i>>5][i&31]=g_ysum[((size_t)b*192+(i>>5))*LL+l0+(i&31)];
  __syncthreads();
  int warp=tid>>5, lane=tid&31;
  for(int q=0;q<4;q++){
    int li=warp*4+q, l=l0+li;
    float s=0.f,s2=0.f,v[6];
    #pragma unroll
    for(int i=0;i<6;i++){ v[i]=t[lane+32*i][li]; s+=v[i]; s2+=v[i]*v[i]; }
    #pragma unroll
    for(int o=16;o;o>>=1){ s+=__shfl_xor_sync(~0u,s,o); s2+=__shfl_xor_sync(~0u,s2,o); }
    float mean=s/192.f, var=s2/192.f-mean*mean, rstd=rsqrtf(var+1e-5f);
    #pragma unroll
    for(int i=0;i<6;i++){ int c=lane+32*i;
      float zz=g_z[((size_t)b*LL+l)*192+c];
      g_ygt[((size_t)b*LL+l)*192+c]=((v[i]-mean)*rstd*g[c]+beta[c])*siluf(zz); }
  }
}

// merged: blocks 0..2 -> weff; blocks 3..98 -> wg/csum/cb2
__global__ __launch_bounds__(256) void prep_all(const float* __restrict__ d1,const float* __restrict__ d3,
                                                const float* __restrict__ d5,const float* __restrict__ fow,
                                                const float* __restrict__ flg,const float* __restrict__ flb,
                                                const float* __restrict__ fob){
  if(blockIdx.x<3){
    int c=blockIdx.x*256+threadIdx.x; if(c>=768) return;
    for(int t=0;t<25;t++){ int dy=t/5,dx=t%5;
      float w=d5[c*25+t];
      if(dy>=1&&dy<=3&&dx>=1&&dx<=3) w+=d3[c*9+(dy-1)*3+(dx-1)];
      if(t==12) w+=d1[c]+1.0f;
      g_weff[t*768+c]=w; }
    return;
  }
  __shared__ float r1[8], r2[8];
  int n=blockIdx.x-3, tid=threadIdx.x;
  float s1=0.f, s2=0.f;
  for(int c=tid;c<768;c+=256){
    float w=fow[n*768+c], wg=w*flg[c];
    g_wg[n*768+c]=wg; s1+=wg; s2+=w*flb[c];
  }
  #pragma unroll
  for(int o=16;o;o>>=1){ s1+=__shfl_xor_sync(~0u,s1,o); s2+=__shfl_xor_sync(~0u,s2,o); }
  int warp=tid>>5, lane=tid&31;
  if(lane==0){ r1[warp]=s1; r2[warp]=s2; }
  __syncthreads();
  if(tid==0){
    float t1=0.f,t2=0.f;
    #pragma unroll
    for(int i=0;i<8;i++){ t1+=r1[i]; t2+=r2[i]; }
    g_csum[n]=t1; g_cb2[n]=t2+fob[n];
  }
}

// fused effective 5x5 depthwise conv + per-pixel partial sum/sumsq over its 64 channels
__global__ __launch_bounds__(512) void conv5(){
  __shared__ float4 tile[8][12][16];
  int cg=blockIdx.x, w0=blockIdx.y*8, b=blockIdx.z>>4, h0=(blockIdx.z&15)*4;
  int tid=threadIdx.x+threadIdx.y*16+threadIdx.z*128;
  for(int t=tid;t<8*12*16;t+=512){
    int r=t/192, cc=(t%192)/16, c4=t&15;
    int h=h0-2+r, w=w0-2+cc;
    float4 v=make_float4(0,0,0,0);
    if(h>=0&&h<64&&w>=0&&w<64)
      v=*(const float4*)(g_hcl+((size_t)(b*LL+h*64+w))*768+cg*64+c4*4);
    tile[r][cc][c4]=v;
  }
  __syncthreads();
  int c4=threadIdx.x, iw=threadIdx.y, ih=threadIdx.z;
  float4 a=make_float4(0,0,0,0);
  #pragma unroll
  for(int dy=0;dy<5;dy++)
    #pragma unroll
    for(int dx=0;dx<5;dx++){
      float4 xv=tile[ih+dy][iw+dx][c4];
      float4 wv=*(const float4*)(g_weff+(dy*5+dx)*768+cg*64+c4*4);
      a.x=fmaf(xv.x,wv.x,a.x); a.y=fmaf(xv.y,wv.y,a.y);
      a.z=fmaf(xv.z,wv.z,a.z); a.w=fmaf(xv.w,wv.w,a.w);
    }
  int px=b*LL+(h0+ih)*64+w0+iw;
  *(float4*)(g_hc2+(size_t)px*768+cg*64+c4*4)=a;
  float s=a.x+a.y+a.z+a.w;
  float s2=a.x*a.x+a.y*a.y+a.z*a.z+a.w*a.w;
  #pragma unroll
  for(int o=1;o<16;o<<=1){ s+=__shfl_xor_sync(~0u,s,o); s2+=__shfl_xor_sync(~0u,s2,o); }
  int lane=tid&31;
  if((lane&15)==0){ g_ps[px*12+cg]=s; g_ps2[px*12+cg]=s2; }
}

extern "C" void kernel_launch(void* const* d_in, const int* in_sizes, int n_in,
                              void* d_out, int out_size){
  const float* x    =(const float*)d_in[0];
  const float* ipw  =(const float*)d_in[1];
  const float* cw   =(const float*)d_in[2];
  const float* cb   =(const float*)d_in[3];
  const float* xpw  =(const float*)d_in[4];
  const float* dtw  =(const float*)d_in[5];
  const float* dtb  =(const float*)d_in[6];
  const float* alogs=(const float*)d_in[7];
  const float* dsv  =(const float*)d_in[8];
  const float* ong  =(const float*)d_in[9];
  const float* onb  =(const float*)d_in[10];
  const float* opw  =(const float*)d_in[11];
  const float* fiw  =(const float*)d_in[12];
  const float* fib  =(const float*)d_in[13];
  const float* fd1  =(const float*)d_in[14];
  const float* fd3  =(const float*)d_in[15];
  const float* fd5  =(const float*)d_in[16];
  const float* flg  =(const float*)d_in[17];
  const float* flb  =(const float*)d_in[18];
  const float* fow  =(const float*)d_in[19];
  const float* fob  =(const float*)d_in[20];
  const float* skip =(const float*)d_in[21];
  float* out=(float*)d_out;

  float *pxilc,*pz,*pygt,*phcl,*phc2,*pwg,*pps,*pps2,*pcs,*pc2;
  cudaGetSymbolAddress((void**)&pxilc,g_xilc);
  cudaGetSymbolAddress((void**)&pz,   g_z);
  cudaGetSymbolAddress((void**)&pygt, g_ygt);
  cudaGetSymbolAddress((void**)&phcl, g_hcl);
  cudaGetSymbolAddress((void**)&phc2, g_hc2);
  cudaGetSymbolAddress((void**)&pwg,  g_wg);
  cudaGetSymbolAddress((void**)&pps,  g_ps);
  cudaGetSymbolAddress((void**)&pps2, g_ps2);
  cudaGetSymbolAddress((void**)&pcs,  g_csum);
  cudaGetSymbolAddress((void**)&pc2,  g_cb2);

  prep_all<<<99,256>>>(fd1,fd3,fd5,fow,flg,flb,fob);
  gemm_tc<4><<<dim3(3,128),256>>>(x, ipw, pxilc, pz, 16384,384,96, nullptr,nullptr,nullptr,nullptr,nullptr,nullptr);
  t_xi<<<dim3(6,128,4),dim3(32,8)>>>();
  conv3t<<<768,256>>>(cw,cb);
  xproj2<<<dim3(32,16),256>>>(xpw);
  scan3<<<384,128>>>(alogs,dsv,dtw,dtb);
  combine<<<dim3(2,2,768),dim3(32,8)>>>();
  ln_gate<<<dim3(128,4),256>>>(ong,onb);
  gemm_tc<0><<<dim3(1,128),256>>>(pygt, opw, out, nullptr, 16384,96,192, nullptr,nullptr,nullptr,nullptr,nullptr,nullptr);
  gemm_tc<1><<<dim3(6,128),256>>>(pygt, fiw, phcl, nullptr, 16384,768,192, fib,nullptr,nullptr,nullptr,nullptr,nullptr);
  conv5<<<dim3(12,8,64),dim3(16,8,4)>>>();
  gemm_tc<3><<<dim3(1,128),256>>>(phc2, pwg, out, nullptr, 16384,96,768, nullptr,skip,pps,pps2,pcs,pc2);
}

// round 13
// speedup vs baseline: 1.1280x; 1.0042x over previous
#include <cuda_runtime.h>
#include <math.h>
#define LL 4096

__device__ __align__(16) float g_xilc[16384*192];
__device__ __align__(16) float g_z   [16384*192];
__device__ __align__(16) float g_xi  [768*LL];
__device__ __align__(16) float g_xc  [768*LL];
__device__ __align__(16) float g_xcT [768*LL];
__device__ __align__(16) float g_xdbl[16*LL*40];
__device__ __align__(16) float g_ys  [16*192*LL];
__device__ __align__(16) float g_ysum[768*LL];
__device__ __align__(16) float g_ygt [16384*192];
__device__ __align__(16) float g_hcl [16384*768];
__device__ __align__(16) float g_hc2 [16384*768];
__device__ __align__(16) float g_weff[25*768];
__device__ __align__(16) float g_wg  [96*768];
__device__ __align__(16) float g_wcat[864*192];
__device__ __align__(16) float g_ps  [16384*12];
__device__ __align__(16) float g_ps2 [16384*12];
__device__ float g_csum[96];
__device__ float g_cb2 [96];

__device__ __forceinline__ float siluf(float v){ return v/(1.f+__expf(-v)); }
__device__ __forceinline__ unsigned f2tf(float f){ unsigned u; asm("cvt.rna.tf32.f32 %0, %1;":"=r"(u):"f"(f)); return u; }
__device__ __forceinline__ void mma8(float* c, unsigned a0,unsigned a1,unsigned a2,unsigned a3,
                                     unsigned b0,unsigned b1){
  asm("mma.sync.aligned.m16n8k8.row.col.f32.tf32.tf32.f32 "
      "{%0,%1,%2,%3},{%4,%5,%6,%7},{%8,%9},{%0,%1,%2,%3};"
      : "+f"(c[0]),"+f"(c[1]),"+f"(c[2]),"+f"(c[3])
      : "r"(a0),"r"(a1),"r"(a2),"r"(a3),"r"(b0),"r"(b1));
}

// C[M,N] = A[M,K]@W[N,K]^T, tf32 tensor cores. 128x128x16 tile, 8 warps (2m x 4n).
// MODE 0: plain   1: bias+silu
// MODE 3: C += skip[0]*((v - mean_m*csum[n])*rstd_m + cb2[n]); mean/rstd from ps/ps2 partials
// MODE 4: split write: col<192 -> C[m*192+col], col>=192 -> C2[m*192+col-192]
// MODE 5: col<96 -> C[m*96+col] plain; col>=96 -> C2[m*768+col-96] = silu(v+bias[col-96])
template<int MODE>
__global__ __launch_bounds__(256,2) void gemm_tc(
  const float* __restrict__ A, const float* __restrict__ W, float* __restrict__ C,
  float* __restrict__ C2,
  int M, int N, int K, const float* __restrict__ bias, const float* __restrict__ skip,
  const float* __restrict__ ps, const float* __restrict__ ps2,
  const float* __restrict__ csum, const float* __restrict__ cb2)
{
  __shared__ unsigned As[128*20];
  __shared__ unsigned Bs[128*20];
  __shared__ float smn[128], srs[128];
  int tid=threadIdx.x, lane=tid&31, warp=tid>>5;
  int wm=warp>>2, wn=warp&3;
  int m0=blockIdx.y*128, n0=blockIdx.x*128;
  int lr=lane>>2, lc=lane&3;
  float acc[4][4][4];
  #pragma unroll
  for(int a=0;a<4;a++)
    #pragma unroll
    for(int b=0;b<4;b++)
      #pragma unroll
      for(int q=0;q<4;q++) acc[a][b][q]=0.f;

  if(MODE==3 && tid<128){
    float s=0.f,s2=0.f;
    #pragma unroll
    for(int j=0;j<12;j++){ s+=ps[(size_t)(m0+tid)*12+j]; s2+=ps2[(size_t)(m0+tid)*12+j]; }
    float mean=s*(1.f/768.f), var=s2*(1.f/768.f)-mean*mean;
    smn[tid]=mean; srs[tid]=rsqrtf(var+1e-5f);
  }

  int row0=tid>>2, t0=tid&3;
  float4 ra[2], rb[2];
  #pragma unroll
  for(int i=0;i<2;i++){
    int row=row0+i*64;
    ra[i]=*(const float4*)(A+(size_t)(m0+row)*K + t0*4);
    int br=n0+row;
    rb[i]= (br<N) ? *(const float4*)(W+(size_t)br*K + t0*4) : make_float4(0,0,0,0);
  }
  for(int k0=0;k0<K;k0+=16){
    #pragma unroll
    for(int i=0;i<2;i++){
      int row=row0+i*64;
      unsigned* p=&As[row*20];
      p[t0]=f2tf(ra[i].x); p[4+t0]=f2tf(ra[i].y); p[8+t0]=f2tf(ra[i].z); p[12+t0]=f2tf(ra[i].w);
      unsigned* q=&Bs[row*20];
      q[t0]=f2tf(rb[i].x); q[4+t0]=f2tf(rb[i].y); q[8+t0]=f2tf(rb[i].z); q[12+t0]=f2tf(rb[i].w);
    }
    __syncthreads();
    if(k0+16<K){
      #pragma unroll
      for(int i=0;i<2;i++){
        int row=row0+i*64;
        ra[i]=*(const float4*)(A+(size_t)(m0+row)*K + k0+16 + t0*4);
        int br=n0+row;
        rb[i]= (br<N) ? *(const float4*)(W+(size_t)br*K + k0+16 + t0*4) : make_float4(0,0,0,0);
      }
    }
    uint4 bg[4];
    #pragma unroll
    for(int nt=0;nt<4;nt++) bg[nt]=*(const uint4*)&Bs[(wn*32+nt*8+lr)*20+lc*4];
    #pragma unroll
    for(int mt=0;mt<4;mt++){
      int r0=wm*64+mt*16+lr;
      uint4 f0=*(const uint4*)&As[r0*20+lc*4];
      uint4 f1=*(const uint4*)&As[(r0+8)*20+lc*4];
      #pragma unroll
      for(int nt=0;nt<4;nt++){
        mma8(acc[mt][nt], f0.x,f1.x,f0.y,f1.y, bg[nt].x,bg[nt].y);
        mma8(acc[mt][nt], f0.z,f1.z,f0.w,f1.w, bg[nt].z,bg[nt].w);
      }
    }
    __syncthreads();
  }
  #pragma unroll
  for(int mt=0;mt<4;mt++){
    #pragma unroll
    for(int nt=0;nt<4;nt++){
      int col=n0+wn*32+nt*8+lc*2;
      if(col>=N) continue;
      #pragma unroll
      for(int hh=0;hh<2;hh++){
        int rloc=wm*64+mt*16+lr+hh*8;
        int row=m0+rloc;
        float v0=acc[mt][nt][hh*2], v1=acc[mt][nt][hh*2+1];
        size_t idx=(size_t)row*N+col;
        if(MODE==0){ C[idx]=v0; C[idx+1]=v1; }
        else if(MODE==1){
          v0+=bias[col]; v1+=bias[col+1];
          C[idx]=siluf(v0); C[idx+1]=siluf(v1);
        } else if(MODE==4){
          if(col<192){ C[(size_t)row*192+col]=v0; C[(size_t)row*192+col+1]=v1; }
          else { C2[(size_t)row*192+col-192]=v0; C2[(size_t)row*192+col-191]=v1; }
        } else if(MODE==5){
          if(col<96){ C[(size_t)row*96+col]=v0; C[(size_t)row*96+col+1]=v1; }
          else {
            int c2=col-96;
            v0+=bias[c2]; v1+=bias[c2+1];
            C2[(size_t)row*768+c2]=siluf(v0); C2[(size_t)row*768+c2+1]=siluf(v1);
          }
        } else {
          float sk=skip[0], mn=smn[rloc], rs=srs[rloc];
          C[idx]  += sk*((v0-mn*csum[col  ])*rs + cb2[col  ]);
          C[idx+1]+= sk*((v1-mn*csum[col+1])*rs + cb2[col+1]);
        }
      }
    }
  }
}

// xilc[m,c] -> xi [b][c][l]
__global__ void t_xi(){
  __shared__ float t[32][33];
  int b=blockIdx.z, c0=blockIdx.x*32, l0=blockIdx.y*32, tx=threadIdx.x, ty=threadIdx.y;
  for(int i=0;i<4;i++) t[ty+i*8][tx]=g_xilc[((size_t)b*LL+l0+ty+i*8)*192+c0+tx];
  __syncthreads();
  for(int i=0;i<4;i++) g_xi[((size_t)b*192+c0+ty+i*8)*LL+l0+tx]=t[tx][ty+i*8];
}

// depthwise 3x3 + bias + silu, writes both xc (hw) and xcT (wh) coalesced
__global__ __launch_bounds__(256) void conv3t(const float* __restrict__ cw, const float* __restrict__ cb){
  __shared__ float pl[66*66];
  __shared__ float ot[64*65];
  int bc=blockIdx.x, c=bc%192;
  const float* src=g_xi+(size_t)bc*4096;
  float wr[9];
  #pragma unroll
  for(int i=0;i<9;i++) wr[i]=cw[c*9+i];
  float bv=cb[c];
  for(int i=threadIdx.x;i<4356;i+=256){
    int r=i/66, q=i-r*66, h=r-1, w=q-1;
    pl[i]=(h>=0&&h<64&&w>=0&&w<64)? src[h*64+w] : 0.f;
  }
  __syncthreads();
  float* dst=g_xc+(size_t)bc*4096;
  for(int p=threadIdx.x;p<4096;p+=256){
    int h=p>>6, w=p&63;
    float s=bv;
    #pragma unroll
    for(int dy=0;dy<3;dy++)
      #pragma unroll
      for(int dx=0;dx<3;dx++) s+=pl[(h+dy)*66+w+dx]*wr[dy*3+dx];
    s=siluf(s);
    dst[p]=s; ot[h*65+w]=s;
  }
  __syncthreads();
  float* dT=g_xcT+(size_t)bc*4096;
  for(int p=threadIdx.x;p<4096;p+=256){
    int wq=p>>6, hq=p&63;
    dT[p]=ot[hq*65+wq];
  }
}

// x_dbl[bk][l][40]: cols 0..5 dts, 8..39 B/C interleaved (Bn at 8+2n, Cn at 9+2n)
// Register-blocked: 5c x 4l per thread, L-tile 128, K-chunk 32.
__global__ __launch_bounds__(256) void xproj2(const float* __restrict__ xpw){
  __shared__ float Wsm[40*196];
  __shared__ float Xs[32*128];
  int bk=blockIdx.y, b=bk>>2, k=bk&3, l0=blockIdx.x*128, tid=threadIdx.x;
  const float* src=((k&1)?g_xcT:g_xc)+(size_t)b*192*LL;
  bool flip=(k>=2);
  for(int i=tid;i<40*192;i+=256){
    int c=i/192, d=i-c*192;
    Wsm[c*196+d]=(c<38)? xpw[k*38*192+i] : 0.f;
  }
  int tc=tid&7, tl=tid>>3;
  float acc[5][4];
  #pragma unroll
  for(int ci=0;ci<5;ci++)
    #pragma unroll
    for(int j=0;j<4;j++) acc[ci][j]=0.f;
  for(int ch=0;ch<6;ch++){
    __syncthreads();
    for(int i=tid;i<1024;i+=256){
      int d=i>>5, lq=i&31;
      int dg=ch*32+d;
      if(!flip){
        float4 v=*(const float4*)(src+(size_t)dg*LL+l0+lq*4);
        *(float4*)&Xs[d*128+lq*4]=v;
      } else {
        float4 v=*(const float4*)(src+(size_t)dg*LL+4092-l0-lq*4);
        Xs[d*128+lq*4+0]=v.w; Xs[d*128+lq*4+1]=v.z;
        Xs[d*128+lq*4+2]=v.y; Xs[d*128+lq*4+3]=v.x;
      }
    }
    __syncthreads();
    #pragma unroll
    for(int d4=0;d4<8;d4++){
      float4 x0=*(const float4*)&Xs[(d4*4+0)*128+tl*4];
      float4 x1=*(const float4*)&Xs[(d4*4+1)*128+tl*4];
      float4 x2=*(const float4*)&Xs[(d4*4+2)*128+tl*4];
      float4 x3=*(const float4*)&Xs[(d4*4+3)*128+tl*4];
      #pragma unroll
      for(int ci=0;ci<5;ci++){
        float4 wv=*(const float4*)&Wsm[(tc*5+ci)*196+ch*32+d4*4];
        acc[ci][0]+=wv.x*x0.x+wv.y*x1.x+wv.z*x2.x+wv.w*x3.x;
        acc[ci][1]+=wv.x*x0.y+wv.y*x1.y+wv.z*x2.y+wv.w*x3.y;
        acc[ci][2]+=wv.x*x0.z+wv.y*x1.z+wv.z*x2.z+wv.w*x3.z;
        acc[ci][3]+=wv.x*x0.w+wv.y*x1.w+wv.z*x2.w+wv.w*x3.w;
      }
    }
  }
  #pragma unroll
  for(int ci=0;ci<5;ci++){
    int c=tc*5+ci; if(c>=38) continue;
    int col=(c<6)?c:(c<22?(8+2*(c-6)):(9+2*(c-22)));
    #pragma unroll
    for(int j=0;j<4;j++){
      int l=l0+tl*4+j;
      g_xdbl[((size_t)bk*LL+l)*40+col]=acc[ci][j];
    }
  }
}

// scan with fused delta: block = 4 warps = 8 channels of one bk.
// Stages full 40-col x_dbl rows via cp.async double buffer; computes
// delta = softplus(dts@dtw+dtb) cooperatively into smem per 32-step chunk.
__global__ __launch_bounds__(128) void scan3(const float* __restrict__ A_logs, const float* __restrict__ Ds,
                                             const float* __restrict__ dtw, const float* __restrict__ dtb){
  __shared__ float sbc[2][32][40];
  __shared__ float dsm[32][8];
  __shared__ float ybuf[4][2][32];
  int tid=threadIdx.x, wIB=tid>>5, lane=tid&31;
  int bx=blockIdx.x, bk=bx/24, dgrp=bx%24;
  int b=bk>>2, k=bk&3;
  int half=lane>>4, n=lane&15;
  int d=dgrp*8+wIB*2+half, kd=k*192+d;
  float Av=-__expf(A_logs[kd*16+n]), Dv=Ds[kd];
  const float* xsrc=((k&1)?g_xcT:g_xc)+((size_t)b*192+d)*LL;
  const float* xdb=g_xdbl+(size_t)bk*LL*40;
  bool flip=(k>=2);
  int ch0=(2*tid)&7, ch1=(2*tid+1)&7;
  int dd0=dgrp*8+ch0, dd1=dgrp*8+ch1;
  float w0r[6], w1r[6];
  #pragma unroll
  for(int r=0;r<6;r++){ w0r[r]=dtw[(k*192+dd0)*6+r]; w1r[r]=dtw[(k*192+dd1)*6+r]; }
  float b0v=dtb[k*192+dd0], b1v=dtb[k*192+dd1];
  int l_0=(2*tid)>>3, l_1=(2*tid+1)>>3;
  float h=0.f;
  {
    #pragma unroll
    for(int i=0;i<3;i++){
      int idx=tid+i*128;
      if(idx<320){
        int row=idx/10, seg=idx%10;
        unsigned sa=(unsigned)__cvta_generic_to_shared(&sbc[0][row][seg*4]);
        asm volatile("cp.async.ca.shared.global [%0], [%1], 16;"::"r"(sa),"l"(xdb+row*40+seg*4));
      }
    }
    asm volatile("cp.async.commit_group;");
  }
  for(int ch=0;ch<128;ch++){
    if(ch+1<128){
      const float* s0=xdb+(size_t)(ch+1)*32*40;
      int nb=(ch+1)&1;
      #pragma unroll
      for(int i=0;i<3;i++){
        int idx=tid+i*128;
        if(idx<320){
          int row=idx/10, seg=idx%10;
          unsigned sa=(unsigned)__cvta_generic_to_shared(&sbc[nb][row][seg*4]);
          asm volatile("cp.async.ca.shared.global [%0], [%1], 16;"::"r"(sa),"l"(s0+row*40+seg*4));
        }
      }
      asm volatile("cp.async.commit_group;");
      asm volatile("cp.async.wait_group 1;");
    } else {
      asm volatile("cp.async.wait_group 0;");
    }
    __syncthreads();
    int l0=ch*32, buf=ch&1;
    {
      const float* r0=&sbc[buf][l_0][0];
      float s0=b0v;
      #pragma unroll
      for(int r=0;r<6;r++) s0+=r0[r]*w0r[r];
      dsm[l_0][ch0]=(s0>20.f)?s0:log1pf(__expf(s0));
      const float* r1=&sbc[buf][l_1][0];
      float s1=b1v;
      #pragma unroll
      for(int r=0;r<6;r++) s1+=r1[r]*w1r[r];
      dsm[l_1][ch1]=(s1>20.f)?s1:log1pf(__expf(s1));
    }
    __syncthreads();
    int mych=wIB*2+half;
    #pragma unroll
    for(int s4=0;s4<32;s4+=4){
      int lb=l0+s4;
      float xv[4];
      if(!flip){ float4 x4=*(const float4*)(xsrc+lb); xv[0]=x4.x;xv[1]=x4.y;xv[2]=x4.z;xv[3]=x4.w; }
      else     { float4 x4=*(const float4*)(xsrc+4092-lb); xv[0]=x4.w;xv[1]=x4.z;xv[2]=x4.y;xv[3]=x4.x; }
      #pragma unroll
      for(int i=0;i<4;i++){
        float dl=dsm[s4+i][mych];
        float2 bc=*(const float2*)&sbc[buf][s4+i][8+2*n];
        h=h*__expf(dl*Av)+(dl*xv[i])*bc.x;
        float yp=h*bc.y;
        yp+=__shfl_xor_sync(~0u,yp,1); yp+=__shfl_xor_sync(~0u,yp,2);
        yp+=__shfl_xor_sync(~0u,yp,4); yp+=__shfl_xor_sync(~0u,yp,8);
        if(n==0) ybuf[wIB][half][s4+i]=yp+Dv*xv[i];
      }
    }
    __syncwarp();
    #pragma unroll
    for(int hh=0;hh<2;hh++){
      size_t ob=(((size_t)k*4+b)*192+dgrp*8+wIB*2+hh)*LL;
      int pos=flip?(4095-(l0+lane)):(l0+lane);
      g_ys[ob+pos]=ybuf[wIB][hh][lane];
    }
    __syncthreads();
  }
}

// ysum[b][c][h*64+w] = Y0+Y2 at hw + transpose(Y1+Y3)
__global__ void combine(){
  __shared__ float t[32][33];
  int bc=blockIdx.z, w0=blockIdx.x*32, h0=blockIdx.y*32, tx=threadIdx.x, ty=threadIdx.y;
  const float* Y0=g_ys+(size_t)bc*LL;         const float* Y1=g_ys+(size_t)(768+bc)*LL;
  const float* Y2=g_ys+(size_t)(1536+bc)*LL;  const float* Y3=g_ys+(size_t)(2304+bc)*LL;
  for(int i=0;i<4;i++){ int wl=ty+i*8, j=(w0+wl)*64+h0+tx; t[wl][tx]=Y1[j]+Y3[j]; }
  __syncthreads();
  float* o=g_ysum+(size_t)bc*LL;
  for(int i=0;i<4;i++){ int hl=ty+i*8, l=(h0+hl)*64+w0+tx; o[l]=t[tx][hl]+Y0[l]+Y2[l]; }
}

__global__ __launch_bounds__(256) void ln_gate(const float* __restrict__ g, const float* __restrict__ beta){
  __shared__ float t[192][33];
  int b=blockIdx.y, l0=blockIdx.x*32, tid=threadIdx.x;
  for(int i=tid;i<192*32;i+=256) t[i>>5][i&31]=g_ysum[((size_t)b*192+(i>>5))*LL+l0+(i&31)];
  __syncthreads();
  int warp=tid>>5, lane=tid&31;
  for(int q=0;q<4;q++){
    int li=warp*4+q, l=l0+li;
    float s=0.f,s2=0.f,v[6];
    #pragma unroll
    for(int i=0;i<6;i++){ v[i]=t[lane+32*i][li]; s+=v[i]; s2+=v[i]*v[i]; }
    #pragma unroll
    for(int o=16;o;o>>=1){ s+=__shfl_xor_sync(~0u,s,o); s2+=__shfl_xor_sync(~0u,s2,o); }
    float mean=s/192.f, var=s2/192.f-mean*mean, rstd=rsqrtf(var+1e-5f);
    #pragma unroll
    for(int i=0;i<6;i++){ int c=lane+32*i;
      float zz=g_z[((size_t)b*LL+l)*192+c];
      g_ygt[((size_t)b*LL+l)*192+c]=((v[i]-mean)*rstd*g[c]+beta[c])*siluf(zz); }
  }
}

// merged: blocks 0..2 -> weff; blocks 3..98 -> wg/csum/cb2; blocks 99..179 -> W_cat copy
__global__ __launch_bounds__(256) void prep_all(const float* __restrict__ d1,const float* __restrict__ d3,
                                                const float* __restrict__ d5,const float* __restrict__ fow,
                                                const float* __restrict__ flg,const float* __restrict__ flb,
                                                const float* __restrict__ fob,
                                                const float* __restrict__ opw,const float* __restrict__ fiw){
  if(blockIdx.x>=99){
    int i=(blockIdx.x-99)*2048 + threadIdx.x*8;
    #pragma unroll
    for(int j=0;j<8;j+=4){
      int idx=i+j;
      float4 v = (idx<18432)? *(const float4*)(opw+idx) : *(const float4*)(fiw+idx-18432);
      *(float4*)(g_wcat+idx)=v;
    }
    return;
  }
  if(blockIdx.x<3){
    int c=blockIdx.x*256+threadIdx.x; if(c>=768) return;
    for(int t=0;t<25;t++){ int dy=t/5,dx=t%5;
      float w=d5[c*25+t];
      if(dy>=1&&dy<=3&&dx>=1&&dx<=3) w+=d3[c*9+(dy-1)*3+(dx-1)];
      if(t==12) w+=d1[c]+1.0f;
      g_weff[t*768+c]=w; }
    return;
  }
  __shared__ float r1[8], r2[8];
  int n=blockIdx.x-3, tid=threadIdx.x;
  float s1=0.f, s2=0.f;
  for(int c=tid;c<768;c+=256){
    float w=fow[n*768+c], wg=w*flg[c];
    g_wg[n*768+c]=wg; s1+=wg; s2+=w*flb[c];
  }
  #pragma unroll
  for(int o=16;o;o>>=1){ s1+=__shfl_xor_sync(~0u,s1,o); s2+=__shfl_xor_sync(~0u,s2,o); }
  int warp=tid>>5, lane=tid&31;
  if(lane==0){ r1[warp]=s1; r2[warp]=s2; }
  __syncthreads();
  if(tid==0){
    float t1=0.f,t2=0.f;
    #pragma unroll
    for(int i=0;i<8;i++){ t1+=r1[i]; t2+=r2[i]; }
    g_csum[n]=t1; g_cb2[n]=t2+fob[n];
  }
}

// fused effective 5x5 depthwise conv + per-pixel partial sum/sumsq over its 64 channels
__global__ __launch_bounds__(512) void conv5(){
  __shared__ float4 tile[8][12][16];
  int cg=blockIdx.x, w0=blockIdx.y*8, b=blockIdx.z>>4, h0=(blockIdx.z&15)*4;
  int tid=threadIdx.x+threadIdx.y*16+threadIdx.z*128;
  for(int t=tid;t<8*12*16;t+=512){
    int r=t/192, cc=(t%192)/16, c4=t&15;
    int h=h0-2+r, w=w0-2+cc;
    float4 v=make_float4(0,0,0,0);
    if(h>=0&&h<64&&w>=0&&w<64)
      v=*(const float4*)(g_hcl+((size_t)(b*LL+h*64+w))*768+cg*64+c4*4);
    tile[r][cc][c4]=v;
  }
  __syncthreads();
  int c4=threadIdx.x, iw=threadIdx.y, ih=threadIdx.z;
  float4 a=make_float4(0,0,0,0);
  #pragma unroll
  for(int dy=0;dy<5;dy++)
    #pragma unroll
    for(int dx=0;dx<5;dx++){
      float4 xv=tile[ih+dy][iw+dx][c4];
      float4 wv=*(const float4*)(g_weff+(dy*5+dx)*768+cg*64+c4*4);
      a.x=fmaf(xv.x,wv.x,a.x); a.y=fmaf(xv.y,wv.y,a.y);
      a.z=fmaf(xv.z,wv.z,a.z); a.w=fmaf(xv.w,wv.w,a.w);
    }
  int px=b*LL+(h0+ih)*64+w0+iw;
  *(float4*)(g_hc2+(size_t)px*768+cg*64+c4*4)=a;
  float s=a.x+a.y+a.z+a.w;
  float s2=a.x*a.x+a.y*a.y+a.z*a.z+a.w*a.w;
  #pragma unroll
  for(int o=1;o<16;o<<=1){ s+=__shfl_xor_sync(~0u,s,o); s2+=__shfl_xor_sync(~0u,s2,o); }
  int lane=tid&31;
  if((lane&15)==0){ g_ps[px*12+cg]=s; g_ps2[px*12+cg]=s2; }
}

extern "C" void kernel_launch(void* const* d_in, const int* in_sizes, int n_in,
                              void* d_out, int out_size){
  const float* x    =(const float*)d_in[0];
  const float* ipw  =(const float*)d_in[1];
  const float* cw   =(const float*)d_in[2];
  const float* cb   =(const float*)d_in[3];
  const float* xpw  =(const float*)d_in[4];
  const float* dtw  =(const float*)d_in[5];
  const float* dtb  =(const float*)d_in[6];
  const float* alogs=(const float*)d_in[7];
  const float* dsv  =(const float*)d_in[8];
  const float* ong  =(const float*)d_in[9];
  const float* onb  =(const float*)d_in[10];
  const float* opw  =(const float*)d_in[11];
  const float* fiw  =(const float*)d_in[12];
  const float* fib  =(const float*)d_in[13];
  const float* fd1  =(const float*)d_in[14];
  const float* fd3  =(const float*)d_in[15];
  const float* fd5  =(const float*)d_in[16];
  const float* flg  =(const float*)d_in[17];
  const float* flb  =(const float*)d_in[18];
  const float* fow  =(const float*)d_in[19];
  const float* fob  =(const float*)d_in[20];
  const float* skip =(const float*)d_in[21];
  float* out=(float*)d_out;

  float *pxilc,*pz,*pygt,*phcl,*phc2,*pwg,*pwcat,*pps,*pps2,*pcs,*pc2;
  cudaGetSymbolAddress((void**)&pxilc,g_xilc);
  cudaGetSymbolAddress((void**)&pz,   g_z);
  cudaGetSymbolAddress((void**)&pygt, g_ygt);
  cudaGetSymbolAddress((void**)&phcl, g_hcl);
  cudaGetSymbolAddress((void**)&phc2, g_hc2);
  cudaGetSymbolAddress((void**)&pwg,  g_wg);
  cudaGetSymbolAddress((void**)&pwcat,g_wcat);
  cudaGetSymbolAddress((void**)&pps,  g_ps);
  cudaGetSymbolAddress((void**)&pps2, g_ps2);
  cudaGetSymbolAddress((void**)&pcs,  g_csum);
  cudaGetSymbolAddress((void**)&pc2,  g_cb2);

  prep_all<<<180,256>>>(fd1,fd3,fd5,fow,flg,flb,fob,opw,fiw);
  gemm_tc<4><<<dim3(3,128),256>>>(x, ipw, pxilc, pz, 16384,384,96, nullptr,nullptr,nullptr,nullptr,nullptr,nullptr);
  t_xi<<<dim3(6,128,4),dim3(32,8)>>>();
  conv3t<<<768,256>>>(cw,cb);
  xproj2<<<dim3(32,16),256>>>(xpw);
  scan3<<<384,128>>>(alogs,dsv,dtw,dtb);
  combine<<<dim3(2,2,768),dim3(32,8)>>>();
  ln_gate<<<dim3(128,4),256>>>(ong,onb);
  gemm_tc<5><<<dim3(7,128),256>>>(pygt, pwcat, out, phcl, 16384,864,192, fib,nullptr,nullptr,nullptr,nullptr,nullptr);
  conv5<<<dim3(12,8,64),dim3(16,8,4)>>>();
  gemm_tc<3><<<dim3(1,128),256>>>(phc2, pwg, out, nullptr, 16384,96,768, nullptr,skip,pps,pps2,pcs,pc2);
}

// round 14
// speedup vs baseline: 1.1419x; 1.0123x over previous
#include <cuda_runtime.h>
#include <math.h>
#define LL 4096

__device__ __align__(16) float g_z   [16384*192];
__device__ __align__(16) float g_xi  [768*LL];
__device__ __align__(16) float g_xc  [768*LL];
__device__ __align__(16) float g_xcT [768*LL];
__device__ __align__(16) float g_xdbl[16*LL*40];
__device__ __align__(16) float g_ys  [16*192*LL];
__device__ __align__(16) float g_ysum[768*LL];
__device__ __align__(16) float g_ygt [16384*192];
__device__ __align__(16) float g_hcl [16384*768];
__device__ __align__(16) float g_hc2 [16384*768];
__device__ __align__(16) float g_weff[25*768];
__device__ __align__(16) float g_wg  [96*768];
__device__ __align__(16) float g_wcat[864*192];
__device__ __align__(16) float g_ps  [16384*12];
__device__ __align__(16) float g_ps2 [16384*12];
__device__ float g_csum[96];
__device__ float g_cb2 [96];

__device__ __forceinline__ float siluf(float v){ return v/(1.f+__expf(-v)); }
__device__ __forceinline__ unsigned f2tf(float f){ unsigned u; asm("cvt.rna.tf32.f32 %0, %1;":"=r"(u):"f"(f)); return u; }
__device__ __forceinline__ void mma8(float* c, unsigned a0,unsigned a1,unsigned a2,unsigned a3,
                                     unsigned b0,unsigned b1){
  asm("mma.sync.aligned.m16n8k8.row.col.f32.tf32.tf32.f32 "
      "{%0,%1,%2,%3},{%4,%5,%6,%7},{%8,%9},{%0,%1,%2,%3};"
      : "+f"(c[0]),"+f"(c[1]),"+f"(c[2]),"+f"(c[3])
      : "r"(a0),"r"(a1),"r"(a2),"r"(a3),"r"(b0),"r"(b1));
}

// C[M,N] = A[M,K]@W[N,K]^T, tf32 tensor cores. 128x128x16 tile, 8 warps (2m x 4n).
// MODE 0: plain   1: bias+silu
// MODE 3: C += skip[0]*((v - mean_m*csum[n])*rstd_m + cb2[n]); mean/rstd from ps/ps2 partials
// MODE 5: col<96 -> C[m*96+col] plain; col>=96 -> C2[m*768+col-96] = silu(v+bias[col-96])
// MODE 6: in_proj split: col<192 -> transposed store C[(b*192+col)*4096 + l] (smem-staged),
//         col>=192 -> C2[m*192+col-192] (z, row-major)
template<int MODE>
__global__ __launch_bounds__(256,2) void gemm_tc(
  const float* __restrict__ A, const float* __restrict__ W, float* __restrict__ C,
  float* __restrict__ C2,
  int M, int N, int K, const float* __restrict__ bias, const float* __restrict__ skip,
  const float* __restrict__ ps, const float* __restrict__ ps2,
  const float* __restrict__ csum, const float* __restrict__ cb2)
{
  __shared__ unsigned As[128*20];
  __shared__ unsigned Bs[128*20];
  __shared__ float smn[128], srs[128];
  __shared__ float tsm[2][16][129];
  int tid=threadIdx.x, lane=tid&31, warp=tid>>5;
  int wm=warp>>2, wn=warp&3;
  int m0=blockIdx.y*128, n0=blockIdx.x*128;
  int lr=lane>>2, lc=lane&3;
  float acc[4][4][4];
  #pragma unroll
  for(int a=0;a<4;a++)
    #pragma unroll
    for(int b=0;b<4;b++)
      #pragma unroll
      for(int q=0;q<4;q++) acc[a][b][q]=0.f;

  if(MODE==3 && tid<128){
    float s=0.f,s2=0.f;
    #pragma unroll
    for(int j=0;j<12;j++){ s+=ps[(size_t)(m0+tid)*12+j]; s2+=ps2[(size_t)(m0+tid)*12+j]; }
    float mean=s*(1.f/768.f), var=s2*(1.f/768.f)-mean*mean;
    smn[tid]=mean; srs[tid]=rsqrtf(var+1e-5f);
  }

  int row0=tid>>2, t0=tid&3;
  float4 ra[2], rb[2];
  #pragma unroll
  for(int i=0;i<2;i++){
    int row=row0+i*64;
    ra[i]=*(const float4*)(A+(size_t)(m0+row)*K + t0*4);
    int br=n0+row;
    rb[i]= (br<N) ? *(const float4*)(W+(size_t)br*K + t0*4) : make_float4(0,0,0,0);
  }
  for(int k0=0;k0<K;k0+=16){
    #pragma unroll
    for(int i=0;i<2;i++){
      int row=row0+i*64;
      unsigned* p=&As[row*20];
      p[t0]=f2tf(ra[i].x); p[4+t0]=f2tf(ra[i].y); p[8+t0]=f2tf(ra[i].z); p[12+t0]=f2tf(ra[i].w);
      unsigned* q=&Bs[row*20];
      q[t0]=f2tf(rb[i].x); q[4+t0]=f2tf(rb[i].y); q[8+t0]=f2tf(rb[i].z); q[12+t0]=f2tf(rb[i].w);
    }
    __syncthreads();
    if(k0+16<K){
      #pragma unroll
      for(int i=0;i<2;i++){
        int row=row0+i*64;
        ra[i]=*(const float4*)(A+(size_t)(m0+row)*K + k0+16 + t0*4);
        int br=n0+row;
        rb[i]= (br<N) ? *(const float4*)(W+(size_t)br*K + k0+16 + t0*4) : make_float4(0,0,0,0);
      }
    }
    uint4 bg[4];
    #pragma unroll
    for(int nt=0;nt<4;nt++) bg[nt]=*(const uint4*)&Bs[(wn*32+nt*8+lr)*20+lc*4];
    #pragma unroll
    for(int mt=0;mt<4;mt++){
      int r0=wm*64+mt*16+lr;
      uint4 f0=*(const uint4*)&As[r0*20+lc*4];
      uint4 f1=*(const uint4*)&As[(r0+8)*20+lc*4];
      #pragma unroll
      for(int nt=0;nt<4;nt++){
        mma8(acc[mt][nt], f0.x,f1.x,f0.y,f1.y, bg[nt].x,bg[nt].y);
        mma8(acc[mt][nt], f0.z,f1.z,f0.w,f1.w, bg[nt].z,bg[nt].w);
      }
    }
    __syncthreads();
  }

  if(MODE==6){
    // z half: direct row-major store
    #pragma unroll
    for(int mt=0;mt<4;mt++)
      #pragma unroll
      for(int nt=0;nt<4;nt++){
        int col=n0+wn*32+nt*8+lc*2;
        if(col>=192){
          #pragma unroll
          for(int hh=0;hh<2;hh++){
            int row=m0+wm*64+mt*16+lr+hh*8;
            C2[(size_t)row*192+col-192]=acc[mt][nt][hh*2];
            C2[(size_t)row*192+col-191]=acc[mt][nt][hh*2+1];
          }
        }
      }
    // xi half: smem-staged transpose, coalesced along l
    if(n0<192){
      int b=m0>>12, l0=m0&4095;
      #pragma unroll
      for(int mt=0;mt<4;mt++){
        __syncthreads();
        #pragma unroll
        for(int nt=0;nt<4;nt++){
          int colloc=wn*32+nt*8+lc*2;
          if(n0+colloc<192){
            #pragma unroll
            for(int hh=0;hh<2;hh++){
              int lloc=lr+hh*8;
              tsm[wm][lloc][colloc]  =acc[mt][nt][hh*2];
              tsm[wm][lloc][colloc+1]=acc[mt][nt][hh*2+1];
            }
          }
        }
        __syncthreads();
        int bufi=tid>>7, colloc=tid&127;
        int gcol=n0+colloc;
        if(gcol<192){
          int rbase=bufi*64+mt*16;
          float* dst=C + ((size_t)(b*192+gcol))*4096 + l0 + rbase;
          #pragma unroll
          for(int j=0;j<16;j+=4){
            float4 v=make_float4(tsm[bufi][j][colloc],tsm[bufi][j+1][colloc],
                                 tsm[bufi][j+2][colloc],tsm[bufi][j+3][colloc]);
            *(float4*)(dst+j)=v;
          }
        }
      }
    }
    return;
  }

  #pragma unroll
  for(int mt=0;mt<4;mt++){
    #pragma unroll
    for(int nt=0;nt<4;nt++){
      int col=n0+wn*32+nt*8+lc*2;
      if(col>=N) continue;
      #pragma unroll
      for(int hh=0;hh<2;hh++){
        int rloc=wm*64+mt*16+lr+hh*8;
        int row=m0+rloc;
        float v0=acc[mt][nt][hh*2], v1=acc[mt][nt][hh*2+1];
        size_t idx=(size_t)row*N+col;
        if(MODE==0){ C[idx]=v0; C[idx+1]=v1; }
        else if(MODE==1){
          v0+=bias[col]; v1+=bias[col+1];
          C[idx]=siluf(v0); C[idx+1]=siluf(v1);
        } else if(MODE==5){
          if(col<96){ C[(size_t)row*96+col]=v0; C[(size_t)row*96+col+1]=v1; }
          else {
            int c2=col-96;
            v0+=bias[c2]; v1+=bias[c2+1];
            C2[(size_t)row*768+c2]=siluf(v0); C2[(size_t)row*768+c2+1]=siluf(v1);
          }
        } else {
          float sk=skip[0], mn=smn[rloc], rs=srs[rloc];
          C[idx]  += sk*((v0-mn*csum[col  ])*rs + cb2[col  ]);
          C[idx+1]+= sk*((v1-mn*csum[col+1])*rs + cb2[col+1]);
        }
      }
    }
  }
}

// depthwise 3x3 + bias + silu, writes both xc (hw) and xcT (wh) coalesced
__global__ __launch_bounds__(256) void conv3t(const float* __restrict__ cw, const float* __restrict__ cb){
  __shared__ float pl[66*66];
  __shared__ float ot[64*65];
  int bc=blockIdx.x, c=bc%192;
  const float* src=g_xi+(size_t)bc*4096;
  float wr[9];
  #pragma unroll
  for(int i=0;i<9;i++) wr[i]=cw[c*9+i];
  float bv=cb[c];
  for(int i=threadIdx.x;i<4356;i+=256){
    int r=i/66, q=i-r*66, h=r-1, w=q-1;
    pl[i]=(h>=0&&h<64&&w>=0&&w<64)? src[h*64+w] : 0.f;
  }
  __syncthreads();
  float* dst=g_xc+(size_t)bc*4096;
  for(int p=threadIdx.x;p<4096;p+=256){
    int h=p>>6, w=p&63;
    float s=bv;
    #pragma unroll
    for(int dy=0;dy<3;dy++)
      #pragma unroll
      for(int dx=0;dx<3;dx++) s+=pl[(h+dy)*66+w+dx]*wr[dy*3+dx];
    s=siluf(s);
    dst[p]=s; ot[h*65+w]=s;
  }
  __syncthreads();
  float* dT=g_xcT+(size_t)bc*4096;
  for(int p=threadIdx.x;p<4096;p+=256){
    int wq=p>>6, hq=p&63;
    dT[p]=ot[hq*65+wq];
  }
}

// x_dbl[bk][l][40]: cols 0..5 dts, 8..39 B/C interleaved (Bn at 8+2n, Cn at 9+2n)
// Register-blocked: 5c x 4l per thread, L-tile 128, K-chunk 32.
__global__ __launch_bounds__(256) void xproj2(const float* __restrict__ xpw){
  __shared__ float Wsm[40*196];
  __shared__ float Xs[32*128];
  int bk=blockIdx.y, b=bk>>2, k=bk&3, l0=blockIdx.x*128, tid=threadIdx.x;
  const float* src=((k&1)?g_xcT:g_xc)+(size_t)b*192*LL;
  bool flip=(k>=2);
  for(int i=tid;i<40*192;i+=256){
    int c=i/192, d=i-c*192;
    Wsm[c*196+d]=(c<38)? xpw[k*38*192+i] : 0.f;
  }
  int tc=tid&7, tl=tid>>3;
  float acc[5][4];
  #pragma unroll
  for(int ci=0;ci<5;ci++)
    #pragma unroll
    for(int j=0;j<4;j++) acc[ci][j]=0.f;
  for(int ch=0;ch<6;ch++){
    __syncthreads();
    for(int i=tid;i<1024;i+=256){
      int d=i>>5, lq=i&31;
      int dg=ch*32+d;
      if(!flip){
        float4 v=*(const float4*)(src+(size_t)dg*LL+l0+lq*4);
        *(float4*)&Xs[d*128+lq*4]=v;
      } else {
        float4 v=*(const float4*)(src+(size_t)dg*LL+4092-l0-lq*4);
        Xs[d*128+lq*4+0]=v.w; Xs[d*128+lq*4+1]=v.z;
        Xs[d*128+lq*4+2]=v.y; Xs[d*128+lq*4+3]=v.x;
      }
    }
    __syncthreads();
    #pragma unroll
    for(int d4=0;d4<8;d4++){
      float4 x0=*(const float4*)&Xs[(d4*4+0)*128+tl*4];
      float4 x1=*(const float4*)&Xs[(d4*4+1)*128+tl*4];
      float4 x2=*(const float4*)&Xs[(d4*4+2)*128+tl*4];
      float4 x3=*(const float4*)&Xs[(d4*4+3)*128+tl*4];
      #pragma unroll
      for(int ci=0;ci<5;ci++){
        float4 wv=*(const float4*)&Wsm[(tc*5+ci)*196+ch*32+d4*4];
        acc[ci][0]+=wv.x*x0.x+wv.y*x1.x+wv.z*x2.x+wv.w*x3.x;
        acc[ci][1]+=wv.x*x0.y+wv.y*x1.y+wv.z*x2.y+wv.w*x3.y;
        acc[ci][2]+=wv.x*x0.z+wv.y*x1.z+wv.z*x2.z+wv.w*x3.z;
        acc[ci][3]+=wv.x*x0.w+wv.y*x1.w+wv.z*x2.w+wv.w*x3.w;
      }
    }
  }
  #pragma unroll
  for(int ci=0;ci<5;ci++){
    int c=tc*5+ci; if(c>=38) continue;
    int col=(c<6)?c:(c<22?(8+2*(c-6)):(9+2*(c-22)));
    #pragma unroll
    for(int j=0;j<4;j++){
      int l=l0+tl*4+j;
      g_xdbl[((size_t)bk*LL+l)*40+col]=acc[ci][j];
    }
  }
}

// scan with fused delta: block = 4 warps = 8 channels of one bk.
__global__ __launch_bounds__(128) void scan3(const float* __restrict__ A_logs, const float* __restrict__ Ds,
                                             const float* __restrict__ dtw, const float* __restrict__ dtb){
  __shared__ float sbc[2][32][40];
  __shared__ float dsm[32][8];
  __shared__ float ybuf[4][2][32];
  int tid=threadIdx.x, wIB=tid>>5, lane=tid&31;
  int bx=blockIdx.x, bk=bx/24, dgrp=bx%24;
  int b=bk>>2, k=bk&3;
  int half=lane>>4, n=lane&15;
  int d=dgrp*8+wIB*2+half, kd=k*192+d;
  float Av=-__expf(A_logs[kd*16+n]), Dv=Ds[kd];
  const float* xsrc=((k&1)?g_xcT:g_xc)+((size_t)b*192+d)*LL;
  const float* xdb=g_xdbl+(size_t)bk*LL*40;
  bool flip=(k>=2);
  int ch0=(2*tid)&7, ch1=(2*tid+1)&7;
  int dd0=dgrp*8+ch0, dd1=dgrp*8+ch1;
  float w0r[6], w1r[6];
  #pragma unroll
  for(int r=0;r<6;r++){ w0r[r]=dtw[(k*192+dd0)*6+r]; w1r[r]=dtw[(k*192+dd1)*6+r]; }
  float b0v=dtb[k*192+dd0], b1v=dtb[k*192+dd1];
  int l_0=(2*tid)>>3, l_1=(2*tid+1)>>3;
  float h=0.f;
  {
    #pragma unroll
    for(int i=0;i<3;i++){
      int idx=tid+i*128;
      if(idx<320){
        int row=idx/10, seg=idx%10;
        unsigned sa=(unsigned)__cvta_generic_to_shared(&sbc[0][row][seg*4]);
        asm volatile("cp.async.ca.shared.global [%0], [%1], 16;"::"r"(sa),"l"(xdb+row*40+seg*4));
      }
    }
    asm volatile("cp.async.commit_group;");
  }
  for(int ch=0;ch<128;ch++){
    if(ch+1<128){
      const float* s0=xdb+(size_t)(ch+1)*32*40;
      int nb=(ch+1)&1;
      #pragma unroll
      for(int i=0;i<3;i++){
        int idx=tid+i*128;
        if(idx<320){
          int row=idx/10, seg=idx%10;
          unsigned sa=(unsigned)__cvta_generic_to_shared(&sbc[nb][row][seg*4]);
          asm volatile("cp.async.ca.shared.global [%0], [%1], 16;"::"r"(sa),"l"(s0+row*40+seg*4));
        }
      }
      asm volatile("cp.async.commit_group;");
      asm volatile("cp.async.wait_group 1;");
    } else {
      asm volatile("cp.async.wait_group 0;");
    }
    __syncthreads();
    int l0=ch*32, buf=ch&1;
    {
      const float* r0=&sbc[buf][l_0][0];
      float s0=b0v;
      #pragma unroll
      for(int r=0;r<6;r++) s0+=r0[r]*w0r[r];
      dsm[l_0][ch0]=(s0>20.f)?s0:log1pf(__expf(s0));
      const float* r1=&sbc[buf][l_1][0];
      float s1=b1v;
      #pragma unroll
      for(int r=0;r<6;r++) s1+=r1[r]*w1r[r];
      dsm[l_1][ch1]=(s1>20.f)?s1:log1pf(__expf(s1));
    }
    __syncthreads();
    int mych=wIB*2+half;
    #pragma unroll
    for(int s4=0;s4<32;s4+=4){
      int lb=l0+s4;
      float xv[4];
      if(!flip){ float4 x4=*(const float4*)(xsrc+lb); xv[0]=x4.x;xv[1]=x4.y;xv[2]=x4.z;xv[3]=x4.w; }
      else     { float4 x4=*(const float4*)(xsrc+4092-lb); xv[0]=x4.w;xv[1]=x4.z;xv[2]=x4.y;xv[3]=x4.x; }
      #pragma unroll
      for(int i=0;i<4;i++){
        float dl=dsm[s4+i][mych];
        float2 bc=*(const float2*)&sbc[buf][s4+i][8+2*n];
        h=h*__expf(dl*Av)+(dl*xv[i])*bc.x;
        float yp=h*bc.y;
        yp+=__shfl_xor_sync(~0u,yp,1); yp+=__shfl_xor_sync(~0u,yp,2);
        yp+=__shfl_xor_sync(~0u,yp,4); yp+=__shfl_xor_sync(~0u,yp,8);
        if(n==0) ybuf[wIB][half][s4+i]=yp+Dv*xv[i];
      }
    }
    __syncwarp();
    #pragma unroll
    for(int hh=0;hh<2;hh++){
      size_t ob=(((size_t)k*4+b)*192+dgrp*8+wIB*2+hh)*LL;
      int pos=flip?(4095-(l0+lane)):(l0+lane);
      g_ys[ob+pos]=ybuf[wIB][hh][lane];
    }
    __syncthreads();
  }
}

// ysum[b][c][h*64+w] = Y0+Y2 at hw + transpose(Y1+Y3)
__global__ void combine(){
  __shared__ float t[32][33];
  int bc=blockIdx.z, w0=blockIdx.x*32, h0=blockIdx.y*32, tx=threadIdx.x, ty=threadIdx.y;
  const float* Y0=g_ys+(size_t)bc*LL;         const float* Y1=g_ys+(size_t)(768+bc)*LL;
  const float* Y2=g_ys+(size_t)(1536+bc)*LL;  const float* Y3=g_ys+(size_t)(2304+bc)*LL;
  for(int i=0;i<4;i++){ int wl=ty+i*8, j=(w0+wl)*64+h0+tx; t[wl][tx]=Y1[j]+Y3[j]; }
  __syncthreads();
  float* o=g_ysum+(size_t)bc*LL;
  for(int i=0;i<4;i++){ int hl=ty+i*8, l=(h0+hl)*64+w0+tx; o[l]=t[tx][hl]+Y0[l]+Y2[l]; }
}

__global__ __launch_bounds__(256) void ln_gate(const float* __restrict__ g, const float* __restrict__ beta){
  __shared__ float t[192][33];
  int b=blockIdx.y, l0=blockIdx.x*32, tid=threadIdx.x;
  for(int i=tid;i<192*32;i+=256) t[i>>5][i&31]=g_ysum[((size_t)b*192+(i>>5))*LL+l0+(i&31)];
  __syncthreads();
  int warp=tid>>5, lane=tid&31;
  for(int q=0;q<4;q++){
    int li=warp*4+q, l=l0+li;
    float s=0.f,s2=0.f,v[6];
    #pragma unroll
    for(int i=0;i<6;i++){ v[i]=t[lane+32*i][li]; s+=v[i]; s2+=v[i]*v[i]; }
    #pragma unroll
    for(int o=16;o;o>>=1){ s+=__shfl_xor_sync(~0u,s,o); s2+=__shfl_xor_sync(~0u,s2,o); }
    float mean=s/192.f, var=s2/192.f-mean*mean, rstd=rsqrtf(var+1e-5f);
    #pragma unroll
    for(int i=0;i<6;i++){ int c=lane+32*i;
      float zz=g_z[((size_t)b*LL+l)*192+c];
      g_ygt[((size_t)b*LL+l)*192+c]=((v[i]-mean)*rstd*g[c]+beta[c])*siluf(zz); }
  }
}

// merged: blocks 0..2 -> weff; blocks 3..98 -> wg/csum/cb2; blocks 99..179 -> W_cat copy
__global__ __launch_bounds__(256) void prep_all(const float* __restrict__ d1,const float* __restrict__ d3,
                                                const float* __restrict__ d5,const float* __restrict__ fow,
                                                const float* __restrict__ flg,const float* __restrict__ flb,
                                                const float* __restrict__ fob,
                                                const float* __restrict__ opw,const float* __restrict__ fiw){
  if(blockIdx.x>=99){
    int i=(blockIdx.x-99)*2048 + threadIdx.x*8;
    #pragma unroll
    for(int j=0;j<8;j+=4){
      int idx=i+j;
      float4 v = (idx<18432)? *(const float4*)(opw+idx) : *(const float4*)(fiw+idx-18432);
      *(float4*)(g_wcat+idx)=v;
    }
    return;
  }
  if(blockIdx.x<3){
    int c=blockIdx.x*256+threadIdx.x; if(c>=768) return;
    for(int t=0;t<25;t++){ int dy=t/5,dx=t%5;
      float w=d5[c*25+t];
      if(dy>=1&&dy<=3&&dx>=1&&dx<=3) w+=d3[c*9+(dy-1)*3+(dx-1)];
      if(t==12) w+=d1[c]+1.0f;
      g_weff[t*768+c]=w; }
    return;
  }
  __shared__ float r1[8], r2[8];
  int n=blockIdx.x-3, tid=threadIdx.x;
  float s1=0.f, s2=0.f;
  for(int c=tid;c<768;c+=256){
    float w=fow[n*768+c], wg=w*flg[c];
    g_wg[n*768+c]=wg; s1+=wg; s2+=w*flb[c];
  }
  #pragma unroll
  for(int o=16;o;o>>=1){ s1+=__shfl_xor_sync(~0u,s1,o); s2+=__shfl_xor_sync(~0u,s2,o); }
  int warp=tid>>5, lane=tid&31;
  if(lane==0){ r1[warp]=s1; r2[warp]=s2; }
  __syncthreads();
  if(tid==0){
    float t1=0.f,t2=0.f;
    #pragma unroll
    for(int i=0;i<8;i++){ t1+=r1[i]; t2+=r2[i]; }
    g_csum[n]=t1; g_cb2[n]=t2+fob[n];
  }
}

// fused effective 5x5 depthwise conv + per-pixel partial sum/sumsq over its 64 channels
__global__ __launch_bounds__(512) void conv5(){
  __shared__ float4 tile[8][12][16];
  int cg=blockIdx.x, w0=blockIdx.y*8, b=blockIdx.z>>4, h0=(blockIdx.z&15)*4;
  int tid=threadIdx.x+threadIdx.y*16+threadIdx.z*128;
  for(int t=tid;t<8*12*16;t+=512){
    int r=t/192, cc=(t%192)/16, c4=t&15;
    int h=h0-2+r, w=w0-2+cc;
    float4 v=make_float4(0,0,0,0);
    if(h>=0&&h<64&&w>=0&&w<64)
      v=*(const float4*)(g_hcl+((size_t)(b*LL+h*64+w))*768+cg*64+c4*4);
    tile[r][cc][c4]=v;
  }
  __syncthreads();
  int c4=threadIdx.x, iw=threadIdx.y, ih=threadIdx.z;
  float4 a=make_float4(0,0,0,0);
  #pragma unroll
  for(int dy=0;dy<5;dy++)
    #pragma unroll
    for(int dx=0;dx<5;dx++){
      float4 xv=tile[ih+dy][iw+dx][c4];
      float4 wv=*(const float4*)(g_weff+(dy*5+dx)*768+cg*64+c4*4);
      a.x=fmaf(xv.x,wv.x,a.x); a.y=fmaf(xv.y,wv.y,a.y);
      a.z=fmaf(xv.z,wv.z,a.z); a.w=fmaf(xv.w,wv.w,a.w);
    }
  int px=b*LL+(h0+ih)*64+w0+iw;
  *(float4*)(g_hc2+(size_t)px*768+cg*64+c4*4)=a;
  float s=a.x+a.y+a.z+a.w;
  float s2=a.x*a.x+a.y*a.y+a.z*a.z+a.w*a.w;
  #pragma unroll
  for(int o=1;o<16;o<<=1){ s+=__shfl_xor_sync(~0u,s,o); s2+=__shfl_xor_sync(~0u,s2,o); }
  int lane=tid&31;
  if((lane&15)==0){ g_ps[px*12+cg]=s; g_ps2[px*12+cg]=s2; }
}

extern "C" void kernel_launch(void* const* d_in, const int* in_sizes, int n_in,
                              void* d_out, int out_size){
  const float* x    =(const float*)d_in[0];
  const float* ipw  =(const float*)d_in[1];
  const float* cw   =(const float*)d_in[2];
  const float* cb   =(const float*)d_in[3];
  const float* xpw  =(const float*)d_in[4];
  const float* dtw  =(const float*)d_in[5];
  const float* dtb  =(const float*)d_in[6];
  const float* alogs=(const float*)d_in[7];
  const float* dsv  =(const float*)d_in[8];
  const float* ong  =(const float*)d_in[9];
  const float* onb  =(const float*)d_in[10];
  const float* opw  =(const float*)d_in[11];
  const float* fiw  =(const float*)d_in[12];
  const float* fib  =(const float*)d_in[13];
  const float* fd1  =(const float*)d_in[14];
  const float* fd3  =(const float*)d_in[15];
  const float* fd5  =(const float*)d_in[16];
  const float* flg  =(const float*)d_in[17];
  const float* flb  =(const float*)d_in[18];
  const float* fow  =(const float*)d_in[19];
  const float* fob  =(const float*)d_in[20];
  const float* skip =(const float*)d_in[21];
  float* out=(float*)d_out;

  float *pxi,*pz,*pygt,*phcl,*phc2,*pwg,*pwcat,*pps,*pps2,*pcs,*pc2;
  cudaGetSymbolAddress((void**)&pxi,  g_xi);
  cudaGetSymbolAddress((void**)&pz,   g_z);
  cudaGetSymbolAddress((void**)&pygt, g_ygt);
  cudaGetSymbolAddress((void**)&phcl, g_hcl);
  cudaGetSymbolAddress((void**)&phc2, g_hc2);
  cudaGetSymbolAddress((void**)&pwg,  g_wg);
  cudaGetSymbolAddress((void**)&pwcat,g_wcat);
  cudaGetSymbolAddress((void**)&pps,  g_ps);
  cudaGetSymbolAddress((void**)&pps2, g_ps2);
  cudaGetSymbolAddress((void**)&pcs,  g_csum);
  cudaGetSymbolAddress((void**)&pc2,  g_cb2);

  prep_all<<<180,256>>>(fd1,fd3,fd5,fow,flg,flb,fob,opw,fiw);
  gemm_tc<6><<<dim3(3,128),256>>>(x, ipw, pxi, pz, 16384,384,96, nullptr,nullptr,nullptr,nullptr,nullptr,nullptr);
  conv3t<<<768,256>>>(cw,cb);
  xproj2<<<dim3(32,16),256>>>(xpw);
  scan3<<<384,128>>>(alogs,dsv,dtw,dtb);
  combine<<<dim3(2,2,768),dim3(32,8)>>>();
  ln_gate<<<dim3(128,4),256>>>(ong,onb);
  gemm_tc<5><<<dim3(7,128),256>>>(pygt, pwcat, out, phcl, 16384,864,192, fib,nullptr,nullptr,nullptr,nullptr,nullptr);
  conv5<<<dim3(12,8,64),dim3(16,8,4)>>>();
  gemm_tc<3><<<dim3(1,128),256>>>(phc2, pwg, out, nullptr, 16384,96,768, nullptr,skip,pps,pps2,pcs,pc2);
}